// round 4
// baseline (speedup 1.0000x reference)
#include <cuda_runtime.h>
#include <cuda_bf16.h>
#include <math.h>
#include <stdint.h>

// Problem constants (fixed by setup_inputs)
#define T_SEQ 2048
#define EMB   2048
#define NH    32
#define NKV   8
#define HD    64
#define NBLK  32
#define WIN   256

// Scratch in device globals (no allocation allowed)
__device__ float g_q[T_SEQ * NH * HD];     // [t][h][d]
__device__ float g_k[T_SEQ * NKV * HD];    // [t][kv][d]
__device__ float g_v[T_SEQ * NKV * HD];
__device__ float g_o[T_SEQ * NH * HD];
__device__ int   g_allow[NBLK * NBLK];

// ---------------------------------------------------------------------------
// Decode rw_allow_blocks robustly (bool/int8 vs int32 vs float32).
// ---------------------------------------------------------------------------
__global__ void decode_mask_kernel(const void* p) {
    __shared__ int cnt0, cnt123;
    int tid = threadIdx.x;
    if (tid == 0) { cnt0 = 0; cnt123 = 0; }
    __syncthreads();
    const unsigned char* b = (const unsigned char*)p;
    int l0 = 0, l123 = 0;
    for (int i = tid; i < 1024; i += 256) {
        if (b[i]) { if ((i & 3) == 0) l0++; else l123++; }
    }
    atomicAdd(&cnt0, l0);
    atomicAdd(&cnt123, l123);
    __syncthreads();
    if (cnt123 == 0) {
        const int* a = (const int*)p;
        for (int i = tid; i < 1024; i += 256) g_allow[i] = (a[i] != 0);
    } else if (cnt0 == 0) {
        const float* a = (const float*)p;
        for (int i = tid; i < 1024; i += 256) g_allow[i] = (a[i] != 0.0f);
    } else {
        for (int i = tid; i < 1024; i += 256) g_allow[i] = (b[i] != 0);
    }
}

// ---------------------------------------------------------------------------
// Tensor-core GEMM core (unchanged from R3): C = A * B^T, fp32 in/out,
// bf16 3-term split at fragment-load time, cp.async double buffer.
// ---------------------------------------------------------------------------
#define MMA_BF16(d, a0, a1, a2, a3, b0, b1)                                   \
    asm volatile(                                                             \
        "mma.sync.aligned.m16n8k16.row.col.f32.bf16.bf16.f32 "                \
        "{%0,%1,%2,%3}, {%4,%5,%6,%7}, {%8,%9}, {%0,%1,%2,%3};"               \
        : "+f"(d[0]), "+f"(d[1]), "+f"(d[2]), "+f"(d[3])                      \
        : "r"(a0), "r"(a1), "r"(a2), "r"(a3), "r"(b0), "r"(b1))

__device__ __forceinline__ void cp16(uint32_t saddr, const float* g) {
    asm volatile("cp.async.cg.shared.global [%0], [%1], 16;" :: "r"(saddr), "l"(g));
}
__device__ __forceinline__ void cp_commit() {
    asm volatile("cp.async.commit_group;" ::: "memory");
}

__device__ __forceinline__ void cvt2(float2 f, uint32_t& hi, uint32_t& lo) {
    __nv_bfloat162 h = __floats2bfloat162_rn(f.x, f.y);
    hi = *reinterpret_cast<uint32_t*>(&h);
    __nv_bfloat162 l = __floats2bfloat162_rn(f.x - __bfloat162float(h.x),
                                             f.y - __bfloat162float(h.y));
    lo = *reinterpret_cast<uint32_t*>(&l);
}

#define BK    16
#define SPAD  20

__device__ __forceinline__ void gemm_core(
    const float* __restrict__ A, const float* __restrict__ B,
    float* __restrict__ C, int K, int ldc, int m0, int n0)
{
    __shared__ float sA[2][128][SPAD];
    __shared__ float sB[2][128][SPAD];

    int tid  = threadIdx.x;
    int warp = tid >> 5;
    int lane = tid & 31;
    int wm = warp & 1;
    int wn = warp >> 1;
    int qr = lane >> 2;
    int qc = (lane & 3) * 2;

    float acc[4][4][4];
#pragma unroll
    for (int i = 0; i < 4; i++)
#pragma unroll
        for (int j = 0; j < 4; j++)
#pragma unroll
            for (int e = 0; e < 4; e++) acc[i][j][e] = 0.0f;

    int crow = tid >> 1;
    int ccol = (tid & 1) * 8;
    const float* aSrc = A + (size_t)(m0 + crow) * K + ccol;
    const float* bSrc = B + (size_t)(n0 + crow) * K + ccol;
    uint32_t sa0 = (uint32_t)__cvta_generic_to_shared(&sA[0][crow][ccol]);
    uint32_t sb0 = (uint32_t)__cvta_generic_to_shared(&sB[0][crow][ccol]);
    const uint32_t stgOff = 128 * SPAD * 4;

    const int NITER = K / BK;

    cp16(sa0,      aSrc);     cp16(sa0 + 16, aSrc + 4);
    cp16(sb0,      bSrc);     cp16(sb0 + 16, bSrc + 4);
    cp_commit();

    for (int it = 0; it < NITER; it++) {
        if (it + 1 < NITER) {
            int k0 = (it + 1) * BK;
            uint32_t st = ((it + 1) & 1) * stgOff;
            cp16(sa0 + st,      aSrc + k0);  cp16(sa0 + st + 16, aSrc + k0 + 4);
            cp16(sb0 + st,      bSrc + k0);  cp16(sb0 + st + 16, bSrc + k0 + 4);
            cp_commit();
            asm volatile("cp.async.wait_group 1;" ::: "memory");
        } else {
            asm volatile("cp.async.wait_group 0;" ::: "memory");
        }
        __syncthreads();

        int st = it & 1;
        uint32_t ah[4][4], al[4][4];
#pragma unroll
        for (int mi = 0; mi < 4; mi++) {
            int r = wm * 64 + mi * 16 + qr;
            cvt2(*(const float2*)&sA[st][r][qc],         ah[mi][0], al[mi][0]);
            cvt2(*(const float2*)&sA[st][r + 8][qc],     ah[mi][1], al[mi][1]);
            cvt2(*(const float2*)&sA[st][r][qc + 8],     ah[mi][2], al[mi][2]);
            cvt2(*(const float2*)&sA[st][r + 8][qc + 8], ah[mi][3], al[mi][3]);
        }
#pragma unroll
        for (int ni = 0; ni < 4; ni++) {
            int n = wn * 32 + ni * 8 + qr;
            uint32_t bh0, bl0, bh1, bl1;
            cvt2(*(const float2*)&sB[st][n][qc],     bh0, bl0);
            cvt2(*(const float2*)&sB[st][n][qc + 8], bh1, bl1);
#pragma unroll
            for (int mi = 0; mi < 4; mi++) {
                MMA_BF16(acc[mi][ni], ah[mi][0], ah[mi][1], ah[mi][2], ah[mi][3], bh0, bh1);
                MMA_BF16(acc[mi][ni], ah[mi][0], ah[mi][1], ah[mi][2], ah[mi][3], bl0, bl1);
                MMA_BF16(acc[mi][ni], al[mi][0], al[mi][1], al[mi][2], al[mi][3], bh0, bh1);
            }
        }
        __syncthreads();
    }

#pragma unroll
    for (int mi = 0; mi < 4; mi++) {
#pragma unroll
        for (int ni = 0; ni < 4; ni++) {
            int r = m0 + wm * 64 + mi * 16 + qr;
            int cidx = n0 + wn * 32 + ni * 8 + qc;
            *(float2*)&C[(size_t)r * ldc + cidx] =
                make_float2(acc[mi][ni][0], acc[mi][ni][1]);
            *(float2*)&C[(size_t)(r + 8) * ldc + cidx] =
                make_float2(acc[mi][ni][2], acc[mi][ni][3]);
        }
    }
}

__global__ __launch_bounds__(256)
void qkv_gemm(const float* __restrict__ hs,
              const float* __restrict__ Wq,
              const float* __restrict__ Wk,
              const float* __restrict__ Wv) {
    int bx = blockIdx.x;
    int m0 = blockIdx.y * 128;
    const float* B;
    float* C;
    int ldc, n0;
    if (bx < 16)      { B = Wq; C = g_q; ldc = NH * HD;  n0 = bx * 128; }
    else if (bx < 20) { B = Wk; C = g_k; ldc = NKV * HD; n0 = (bx - 16) * 128; }
    else              { B = Wv; C = g_v; ldc = NKV * HD; n0 = (bx - 20) * 128; }
    gemm_core(hs, B, C, EMB, ldc, m0, n0);
}

__global__ __launch_bounds__(256)
void out_gemm(const float* __restrict__ Wo, float* __restrict__ out) {
    gemm_core(g_o, Wo, out, EMB, EMB, blockIdx.y * 128, blockIdx.x * 128);
}

// ---------------------------------------------------------------------------
// RoPE applied in-place to q and k.
// ---------------------------------------------------------------------------
__global__ void rope_kernel(const float* __restrict__ cosb, const float* __restrict__ sinb) {
    int idx = blockIdx.x * blockDim.x + threadIdx.x;
    const int total = T_SEQ * (NH + NKV) * 32;
    if (idx >= total) return;
    int d = idx & 31;
    int rest = idx >> 5;
    int head = rest % (NH + NKV);
    int t = rest / (NH + NKV);
    float c0 = cosb[t * HD + d];
    float s0 = sinb[t * HD + d];
    float c1 = cosb[t * HD + d + 32];
    float s1 = sinb[t * HD + d + 32];
    float* base = (head < NH) ? (g_q + ((size_t)t * NH + head) * HD)
                              : (g_k + ((size_t)t * NKV + (head - NH)) * HD);
    float x0 = base[d];
    float x1 = base[d + 32];
    base[d]      = x0 * c0 - x1 * s0;
    base[d + 32] = x1 * c1 + x0 * s1;
}

// ---------------------------------------------------------------------------
// Attention v2: 256 threads/block, 4 threads per q-row (16 dims each).
// One-pass online softmax with conditional rescale, quad-shfl score reduce.
// ---------------------------------------------------------------------------
__global__ __launch_bounds__(256)
void attn_kernel() {
    int h  = blockIdx.x;   // 0..31
    int qb = blockIdx.y;   // 0..31
    int tid = threadIdx.x;
    int r  = tid >> 2;     // q-row 0..63
    int c  = tid & 3;      // dim-quadrant
    int d0 = c * 16;
    int kv = h >> 2;
    int qi = qb * 64 + r;

    __shared__ float Kt[64][64];
    __shared__ float Vt[64][64];

    float qreg[16];
    const float* qrow = g_q + ((size_t)qi * NH + h) * HD + d0;
#pragma unroll
    for (int d = 0; d < 16; d++) qreg[d] = qrow[d] * 0.125f;   // fold D^-0.5

    float m = -1e30f, l = 0.0f;
    float acc[16];
#pragma unroll
    for (int d = 0; d < 16; d++) acc[d] = 0.0f;

    for (int kb = 0; kb < NBLK; kb++) {
        int ba = g_allow[qb * NBLK + kb];
        bool win_possible = (kb < 4) || (kb <= qb && kb + 4 >= qb);
        if (!ba && !win_possible) continue;

        __syncthreads();
        // 256 threads load 64x64 K and V tiles (float4 each, 4 per thread)
#pragma unroll
        for (int t = 0; t < 4; t++) {
            int i = tid * 4 + t;          // 0..1023 float4 index
            int row = i >> 4;             // 16 float4 per row
            int col = (i & 15) * 4;
            size_t goff = ((size_t)(kb * 64 + row) * NKV + kv) * HD + col;
            *(float4*)&Kt[row][col] = *(const float4*)&g_k[goff];
            *(float4*)&Vt[row][col] = *(const float4*)&g_v[goff];
        }
        __syncthreads();

        for (int j = 0; j < 64; j++) {
            int kj = kb * 64 + j;
            bool ok = ba || (kj < WIN) || (kj <= qi && kj + (WIN - 1) >= qi);
            float part = 0.0f;
#pragma unroll
            for (int d = 0; d < 16; d++) part += qreg[d] * Kt[j][d0 + d];
            part += __shfl_xor_sync(0xFFFFFFFF, part, 1);
            part += __shfl_xor_sync(0xFFFFFFFF, part, 2);
            if (ok) {
                if (part > m) {
                    float sc = __expf(m - part);
                    m = part;
                    l *= sc;
#pragma unroll
                    for (int d = 0; d < 16; d++) acc[d] *= sc;
                }
                float p = __expf(part - m);
                l += p;
#pragma unroll
                for (int d = 0; d < 16; d++) acc[d] += p * Vt[j][d0 + d];
            }
        }
    }
    float inv = 1.0f / l;   // l > 0 (first 256 keys always allowed)
    float* orow = g_o + ((size_t)qi * NH + h) * HD + d0;
#pragma unroll
    for (int d = 0; d < 16; d++) orow[d] = acc[d] * inv;
}

// ---------------------------------------------------------------------------
extern "C" void kernel_launch(void* const* d_in, const int* in_sizes, int n_in,
                              void* d_out, int out_size) {
    const float* hs   = (const float*)d_in[0];
    const float* cosb = (const float*)d_in[1];
    const float* sinb = (const float*)d_in[2];
    const float* Wq   = (const float*)d_in[3];
    const float* Wk   = (const float*)d_in[4];
    const float* Wv   = (const float*)d_in[5];
    const float* Wo   = (const float*)d_in[6];
    const void*  allow = d_in[7];
    float* out = (float*)d_out;

    decode_mask_kernel<<<1, 256>>>(allow);

    // Fused QKV projection
    qkv_gemm<<<dim3(24, T_SEQ / 128), 256>>>(hs, Wq, Wk, Wv);

    // RoPE
    {
        int total = T_SEQ * (NH + NKV) * 32;
        rope_kernel<<<(total + 255) / 256, 256>>>(cosb, sinb);
    }

    // Masked flash attention (v2)
    attn_kernel<<<dim3(NH, NBLK), 256>>>();

    // Output projection
    out_gemm<<<dim3(EMB / 128, T_SEQ / 128), 256>>>(Wo, out);
}

// round 5
// speedup vs baseline: 3.1015x; 3.1015x over previous
#include <cuda_runtime.h>
#include <cuda_bf16.h>
#include <math.h>
#include <stdint.h>

// Problem constants (fixed by setup_inputs)
#define T_SEQ 2048
#define EMB   2048
#define NH    32
#define NKV   8
#define HD    64
#define NBLK  32
#define WIN   256

// Scratch in device globals (no allocation allowed)
__device__ float g_q[T_SEQ * NH * HD];     // [t][h][d]
__device__ float g_k[T_SEQ * NKV * HD];    // [t][kv][d]
__device__ float g_v[T_SEQ * NKV * HD];
__device__ float g_o[T_SEQ * NH * HD];
__device__ int   g_allow[NBLK * NBLK];

// bf16 hi/lo pre-converted K ([kv][t][d]) and transposed V ([kv][d][t])
__device__ __nv_bfloat16 g_kh[NKV * T_SEQ * HD];
__device__ __nv_bfloat16 g_kl[NKV * T_SEQ * HD];
__device__ __nv_bfloat16 g_vh[NKV * HD * T_SEQ];
__device__ __nv_bfloat16 g_vl[NKV * HD * T_SEQ];

// ---------------------------------------------------------------------------
// Decode rw_allow_blocks robustly (bool/int8 vs int32 vs float32).
// ---------------------------------------------------------------------------
__global__ void decode_mask_kernel(const void* p) {
    __shared__ int cnt0, cnt123;
    int tid = threadIdx.x;
    if (tid == 0) { cnt0 = 0; cnt123 = 0; }
    __syncthreads();
    const unsigned char* b = (const unsigned char*)p;
    int l0 = 0, l123 = 0;
    for (int i = tid; i < 1024; i += 256) {
        if (b[i]) { if ((i & 3) == 0) l0++; else l123++; }
    }
    atomicAdd(&cnt0, l0);
    atomicAdd(&cnt123, l123);
    __syncthreads();
    if (cnt123 == 0) {
        const int* a = (const int*)p;
        for (int i = tid; i < 1024; i += 256) g_allow[i] = (a[i] != 0);
    } else if (cnt0 == 0) {
        const float* a = (const float*)p;
        for (int i = tid; i < 1024; i += 256) g_allow[i] = (a[i] != 0.0f);
    } else {
        for (int i = tid; i < 1024; i += 256) g_allow[i] = (b[i] != 0);
    }
}

// ---------------------------------------------------------------------------
// Shared helpers
// ---------------------------------------------------------------------------
#define MMA_BF16(d, a0, a1, a2, a3, b0, b1)                                   \
    asm volatile(                                                             \
        "mma.sync.aligned.m16n8k16.row.col.f32.bf16.bf16.f32 "                \
        "{%0,%1,%2,%3}, {%4,%5,%6,%7}, {%8,%9}, {%0,%1,%2,%3};"               \
        : "+f"(d[0]), "+f"(d[1]), "+f"(d[2]), "+f"(d[3])                      \
        : "r"(a0), "r"(a1), "r"(a2), "r"(a3), "r"(b0), "r"(b1))

__device__ __forceinline__ void cp16(uint32_t saddr, const void* g) {
    asm volatile("cp.async.cg.shared.global [%0], [%1], 16;" :: "r"(saddr), "l"(g));
}
__device__ __forceinline__ void cp_commit() {
    asm volatile("cp.async.commit_group;" ::: "memory");
}

__device__ __forceinline__ void cvt2(float2 f, uint32_t& hi, uint32_t& lo) {
    __nv_bfloat162 h = __floats2bfloat162_rn(f.x, f.y);
    hi = *reinterpret_cast<uint32_t*>(&h);
    __nv_bfloat162 l = __floats2bfloat162_rn(f.x - __bfloat162float(h.x),
                                             f.y - __bfloat162float(h.y));
    lo = *reinterpret_cast<uint32_t*>(&l);
}

// ---------------------------------------------------------------------------
// Tensor-core GEMM core (unchanged, proven): C = A * B^T, fp32 in/out.
// ---------------------------------------------------------------------------
#define BK    16
#define SPAD  20

__device__ __forceinline__ void gemm_core(
    const float* __restrict__ A, const float* __restrict__ B,
    float* __restrict__ C, int K, int ldc, int m0, int n0)
{
    __shared__ float sA[2][128][SPAD];
    __shared__ float sB[2][128][SPAD];

    int tid  = threadIdx.x;
    int warp = tid >> 5;
    int lane = tid & 31;
    int wm = warp & 1;
    int wn = warp >> 1;
    int qr = lane >> 2;
    int qc = (lane & 3) * 2;

    float acc[4][4][4];
#pragma unroll
    for (int i = 0; i < 4; i++)
#pragma unroll
        for (int j = 0; j < 4; j++)
#pragma unroll
            for (int e = 0; e < 4; e++) acc[i][j][e] = 0.0f;

    int crow = tid >> 1;
    int ccol = (tid & 1) * 8;
    const float* aSrc = A + (size_t)(m0 + crow) * K + ccol;
    const float* bSrc = B + (size_t)(n0 + crow) * K + ccol;
    uint32_t sa0 = (uint32_t)__cvta_generic_to_shared(&sA[0][crow][ccol]);
    uint32_t sb0 = (uint32_t)__cvta_generic_to_shared(&sB[0][crow][ccol]);
    const uint32_t stgOff = 128 * SPAD * 4;

    const int NITER = K / BK;

    cp16(sa0,      aSrc);     cp16(sa0 + 16, aSrc + 4);
    cp16(sb0,      bSrc);     cp16(sb0 + 16, bSrc + 4);
    cp_commit();

    for (int it = 0; it < NITER; it++) {
        if (it + 1 < NITER) {
            int k0 = (it + 1) * BK;
            uint32_t st = ((it + 1) & 1) * stgOff;
            cp16(sa0 + st,      aSrc + k0);  cp16(sa0 + st + 16, aSrc + k0 + 4);
            cp16(sb0 + st,      bSrc + k0);  cp16(sb0 + st + 16, bSrc + k0 + 4);
            cp_commit();
            asm volatile("cp.async.wait_group 1;" ::: "memory");
        } else {
            asm volatile("cp.async.wait_group 0;" ::: "memory");
        }
        __syncthreads();

        int st = it & 1;
        uint32_t ah[4][4], al[4][4];
#pragma unroll
        for (int mi = 0; mi < 4; mi++) {
            int r = wm * 64 + mi * 16 + qr;
            cvt2(*(const float2*)&sA[st][r][qc],         ah[mi][0], al[mi][0]);
            cvt2(*(const float2*)&sA[st][r + 8][qc],     ah[mi][1], al[mi][1]);
            cvt2(*(const float2*)&sA[st][r][qc + 8],     ah[mi][2], al[mi][2]);
            cvt2(*(const float2*)&sA[st][r + 8][qc + 8], ah[mi][3], al[mi][3]);
        }
#pragma unroll
        for (int ni = 0; ni < 4; ni++) {
            int n = wn * 32 + ni * 8 + qr;
            uint32_t bh0, bl0, bh1, bl1;
            cvt2(*(const float2*)&sB[st][n][qc],     bh0, bl0);
            cvt2(*(const float2*)&sB[st][n][qc + 8], bh1, bl1);
#pragma unroll
            for (int mi = 0; mi < 4; mi++) {
                MMA_BF16(acc[mi][ni], ah[mi][0], ah[mi][1], ah[mi][2], ah[mi][3], bh0, bh1);
                MMA_BF16(acc[mi][ni], ah[mi][0], ah[mi][1], ah[mi][2], ah[mi][3], bl0, bl1);
                MMA_BF16(acc[mi][ni], al[mi][0], al[mi][1], al[mi][2], al[mi][3], bh0, bh1);
            }
        }
        __syncthreads();
    }

#pragma unroll
    for (int mi = 0; mi < 4; mi++) {
#pragma unroll
        for (int ni = 0; ni < 4; ni++) {
            int r = m0 + wm * 64 + mi * 16 + qr;
            int cidx = n0 + wn * 32 + ni * 8 + qc;
            *(float2*)&C[(size_t)r * ldc + cidx] =
                make_float2(acc[mi][ni][0], acc[mi][ni][1]);
            *(float2*)&C[(size_t)(r + 8) * ldc + cidx] =
                make_float2(acc[mi][ni][2], acc[mi][ni][3]);
        }
    }
}

__global__ __launch_bounds__(256)
void qkv_gemm(const float* __restrict__ hs,
              const float* __restrict__ Wq,
              const float* __restrict__ Wk,
              const float* __restrict__ Wv) {
    int bx = blockIdx.x;
    int m0 = blockIdx.y * 128;
    const float* B;
    float* C;
    int ldc, n0;
    if (bx < 16)      { B = Wq; C = g_q; ldc = NH * HD;  n0 = bx * 128; }
    else if (bx < 20) { B = Wk; C = g_k; ldc = NKV * HD; n0 = (bx - 16) * 128; }
    else              { B = Wv; C = g_v; ldc = NKV * HD; n0 = (bx - 20) * 128; }
    gemm_core(hs, B, C, EMB, ldc, m0, n0);
}

__global__ __launch_bounds__(256)
void out_gemm(const float* __restrict__ Wo, float* __restrict__ out) {
    gemm_core(g_o, Wo, out, EMB, EMB, blockIdx.y * 128, blockIdx.x * 128);
}

// ---------------------------------------------------------------------------
// RoPE applied in-place to q and k.
// ---------------------------------------------------------------------------
__global__ void rope_kernel(const float* __restrict__ cosb, const float* __restrict__ sinb) {
    int idx = blockIdx.x * blockDim.x + threadIdx.x;
    const int total = T_SEQ * (NH + NKV) * 32;
    if (idx >= total) return;
    int d = idx & 31;
    int rest = idx >> 5;
    int head = rest % (NH + NKV);
    int t = rest / (NH + NKV);
    float c0 = cosb[t * HD + d];
    float s0 = sinb[t * HD + d];
    float c1 = cosb[t * HD + d + 32];
    float s1 = sinb[t * HD + d + 32];
    float* base = (head < NH) ? (g_q + ((size_t)t * NH + head) * HD)
                              : (g_k + ((size_t)t * NKV + (head - NH)) * HD);
    float x0 = base[d];
    float x1 = base[d + 32];
    base[d]      = x0 * c0 - x1 * s0;
    base[d + 32] = x1 * c1 + x0 * s1;
}

// ---------------------------------------------------------------------------
// Prep: K (post-RoPE) -> bf16 hi/lo [kv][t][d]; V -> transposed [kv][d][t].
// ---------------------------------------------------------------------------
__global__ void prep_k_kernel() {
    int o = blockIdx.x * blockDim.x + threadIdx.x;
    if (o >= NKV * T_SEQ * HD) return;
    int d  = o & 63;
    int t  = (o >> 6) & (T_SEQ - 1);
    int kv = o >> 17;
    float v = g_k[((size_t)t * NKV + kv) * HD + d];
    __nv_bfloat16 h = __float2bfloat16(v);
    g_kh[o] = h;
    g_kl[o] = __float2bfloat16(v - __bfloat162float(h));
}

__global__ void prep_v_kernel() {
    int o = blockIdx.x * blockDim.x + threadIdx.x;
    if (o >= NKV * HD * T_SEQ) return;
    int t  = o & (T_SEQ - 1);
    int d  = (o >> 11) & 63;
    int kv = o >> 17;
    float v = g_v[((size_t)t * NKV + kv) * HD + d];
    __nv_bfloat16 h = __float2bfloat16(v);
    g_vh[o] = h;
    g_vl[o] = __float2bfloat16(v - __bfloat162float(h));
}

// ---------------------------------------------------------------------------
// MMA flash attention. CTA = (head, 64-row q-block), 4 warps x 16 rows.
// Tiles: sT[0]=Kh, sT[1]=Kl (rows j, cols d), sT[2]=Vh, sT[3]=Vl (rows d, cols j).
// Stride 72 bf16 -> conflict-free b-frag loads.
// ---------------------------------------------------------------------------
#define TSTR 72

__global__ __launch_bounds__(128)
void attn_mma_kernel() {
    __shared__ __align__(16) __nv_bfloat16 sT[4][64][TSTR];

    int h  = blockIdx.x;
    int qb = blockIdx.y;
    int kv = h >> 2;
    int tid  = threadIdx.x;
    int w    = tid >> 5;
    int lane = tid & 31;
    int qr   = lane >> 2;
    int qc2  = (lane & 3) * 2;
    int rowA = w * 16 + qr;              // warp-local q row (and +8)

    // ---- stage Q tile (fp32, pre-scaled) into smem, build A-frags, free smem
    float* sQ = (float*)&sT[0][0][0];    // 64 x 68 floats (17.4KB < 36.9KB)
    for (int i = tid; i < 64 * 16; i += 128) {
        int row = i >> 4;
        int c4  = (i & 15) * 4;
        float4 v = *(const float4*)&g_q[(((size_t)qb * 64 + row) * NH + h) * HD + c4];
        v.x *= 0.125f; v.y *= 0.125f; v.z *= 0.125f; v.w *= 0.125f;
        *(float4*)&sQ[row * 68 + c4] = v;
    }
    __syncthreads();

    uint32_t qh[4][4], ql[4][4];
#pragma unroll
    for (int kc = 0; kc < 4; kc++) {
        int k = kc * 16 + qc2;
        cvt2(*(const float2*)&sQ[rowA * 68 + k],           qh[kc][0], ql[kc][0]);
        cvt2(*(const float2*)&sQ[(rowA + 8) * 68 + k],     qh[kc][1], ql[kc][1]);
        cvt2(*(const float2*)&sQ[rowA * 68 + k + 8],       qh[kc][2], ql[kc][2]);
        cvt2(*(const float2*)&sQ[(rowA + 8) * 68 + k + 8], qh[kc][3], ql[kc][3]);
    }
    __syncthreads();

    float m0 = -1e30f, m1 = -1e30f, l0 = 0.0f, l1 = 0.0f;
    float o[8][4];
#pragma unroll
    for (int ni = 0; ni < 8; ni++)
#pragma unroll
        for (int e = 0; e < 4; e++) o[ni][e] = 0.0f;

    for (int kb = 0; kb < NBLK; kb++) {
        int ba = g_allow[qb * NBLK + kb];
        bool win_possible = (kb < 4) || (kb <= qb && kb + 4 >= qb);
        if (!ba && !win_possible) continue;

        // ---- cp.async load Kh,Kl (rows j) and Vh,Vl (rows d) tiles ----
#pragma unroll
        for (int t = 0; t < 16; t++) {
            int id   = t * 128 + tid;       // 0..2047
            int tile = id >> 9;             // 0..3
            int row  = (id >> 3) & 63;
            int ch   = id & 7;
            const __nv_bfloat16* src;
            if (tile == 0)
                src = g_kh + (((size_t)kv * T_SEQ + kb * 64 + row) * HD + ch * 8);
            else if (tile == 1)
                src = g_kl + (((size_t)kv * T_SEQ + kb * 64 + row) * HD + ch * 8);
            else if (tile == 2)
                src = g_vh + (((size_t)kv * HD + row) * T_SEQ + kb * 64 + ch * 8);
            else
                src = g_vl + (((size_t)kv * HD + row) * T_SEQ + kb * 64 + ch * 8);
            cp16((uint32_t)__cvta_generic_to_shared(&sT[tile][row][ch * 8]), src);
        }
        cp_commit();
        asm volatile("cp.async.wait_group 0;" ::: "memory");
        __syncthreads();

        // ---- S = Q K^T (3-term bf16) ----
        float s[8][4];
#pragma unroll
        for (int ni = 0; ni < 8; ni++) {
#pragma unroll
            for (int e = 0; e < 4; e++) s[ni][e] = 0.0f;
            int n = ni * 8 + qr;
#pragma unroll
            for (int kc = 0; kc < 4; kc++) {
                int kcol = kc * 16 + qc2;
                uint32_t bh0 = *(const uint32_t*)&sT[0][n][kcol];
                uint32_t bh1 = *(const uint32_t*)&sT[0][n][kcol + 8];
                uint32_t bl0 = *(const uint32_t*)&sT[1][n][kcol];
                uint32_t bl1 = *(const uint32_t*)&sT[1][n][kcol + 8];
                MMA_BF16(s[ni], qh[kc][0], qh[kc][1], qh[kc][2], qh[kc][3], bh0, bh1);
                MMA_BF16(s[ni], qh[kc][0], qh[kc][1], qh[kc][2], qh[kc][3], bl0, bl1);
                MMA_BF16(s[ni], ql[kc][0], ql[kc][1], ql[kc][2], ql[kc][3], bh0, bh1);
            }
        }

        // ---- mask ----
        int qi0 = qb * 64 + rowA;
        int qi1 = qi0 + 8;
#pragma unroll
        for (int ni = 0; ni < 8; ni++) {
            int col = kb * 64 + ni * 8 + qc2;
#pragma unroll
            for (int e = 0; e < 4; e++) {
                int kj = col + (e & 1);
                int qi = (e < 2) ? qi0 : qi1;
                bool ok = ba || (kj < WIN) || (kj <= qi && kj + (WIN - 1) >= qi);
                if (!ok) s[ni][e] = -1e30f;
            }
        }

        // ---- online softmax (row-wise across quad) ----
        float mb0 = -1e30f, mb1 = -1e30f;
#pragma unroll
        for (int ni = 0; ni < 8; ni++) {
            mb0 = fmaxf(mb0, fmaxf(s[ni][0], s[ni][1]));
            mb1 = fmaxf(mb1, fmaxf(s[ni][2], s[ni][3]));
        }
        mb0 = fmaxf(mb0, __shfl_xor_sync(0xFFFFFFFF, mb0, 1));
        mb0 = fmaxf(mb0, __shfl_xor_sync(0xFFFFFFFF, mb0, 2));
        mb1 = fmaxf(mb1, __shfl_xor_sync(0xFFFFFFFF, mb1, 1));
        mb1 = fmaxf(mb1, __shfl_xor_sync(0xFFFFFFFF, mb1, 2));

        float mn0 = fmaxf(m0, mb0), mn1 = fmaxf(m1, mb1);
        float sc0 = __expf(m0 - mn0), sc1 = __expf(m1 - mn1);
        m0 = mn0; m1 = mn1;
        l0 *= sc0; l1 *= sc1;
#pragma unroll
        for (int ni = 0; ni < 8; ni++) {
            o[ni][0] *= sc0; o[ni][1] *= sc0;
            o[ni][2] *= sc1; o[ni][3] *= sc1;
        }

        // p = exp(s - m), accumulate l (thread-partial)
#pragma unroll
        for (int ni = 0; ni < 8; ni++) {
            s[ni][0] = __expf(s[ni][0] - m0);
            s[ni][1] = __expf(s[ni][1] - m0);
            s[ni][2] = __expf(s[ni][2] - m1);
            s[ni][3] = __expf(s[ni][3] - m1);
            l0 += s[ni][0] + s[ni][1];
            l1 += s[ni][2] + s[ni][3];
        }

        // ---- O += P V (3-term bf16), P frags straight from s registers ----
#pragma unroll
        for (int kc = 0; kc < 4; kc++) {
            uint32_t ah[4], al[4];
            cvt2(make_float2(s[2 * kc][0],     s[2 * kc][1]),     ah[0], al[0]);
            cvt2(make_float2(s[2 * kc][2],     s[2 * kc][3]),     ah[1], al[1]);
            cvt2(make_float2(s[2 * kc + 1][0], s[2 * kc + 1][1]), ah[2], al[2]);
            cvt2(make_float2(s[2 * kc + 1][2], s[2 * kc + 1][3]), ah[3], al[3]);
#pragma unroll
            for (int ni = 0; ni < 8; ni++) {
                int n = ni * 8 + qr;
                int kcol = kc * 16 + qc2;
                uint32_t bh0 = *(const uint32_t*)&sT[2][n][kcol];
                uint32_t bh1 = *(const uint32_t*)&sT[2][n][kcol + 8];
                uint32_t bl0 = *(const uint32_t*)&sT[3][n][kcol];
                uint32_t bl1 = *(const uint32_t*)&sT[3][n][kcol + 8];
                MMA_BF16(o[ni], ah[0], ah[1], ah[2], ah[3], bh0, bh1);
                MMA_BF16(o[ni], ah[0], ah[1], ah[2], ah[3], bl0, bl1);
                MMA_BF16(o[ni], al[0], al[1], al[2], al[3], bh0, bh1);
            }
        }
        __syncthreads();   // tiles consumed before next kb overwrites
    }

    // ---- finalize: reduce l across quad, normalize, write ----
    l0 += __shfl_xor_sync(0xFFFFFFFF, l0, 1);
    l0 += __shfl_xor_sync(0xFFFFFFFF, l0, 2);
    l1 += __shfl_xor_sync(0xFFFFFFFF, l1, 1);
    l1 += __shfl_xor_sync(0xFFFFFFFF, l1, 2);
    float inv0 = 1.0f / l0, inv1 = 1.0f / l1;

    int qi0 = qb * 64 + rowA;
#pragma unroll
    for (int ni = 0; ni < 8; ni++) {
        int d = ni * 8 + qc2;
        *(float2*)&g_o[((size_t)qi0 * NH + h) * HD + d] =
            make_float2(o[ni][0] * inv0, o[ni][1] * inv0);
        *(float2*)&g_o[((size_t)(qi0 + 8) * NH + h) * HD + d] =
            make_float2(o[ni][2] * inv1, o[ni][3] * inv1);
    }
}

// ---------------------------------------------------------------------------
extern "C" void kernel_launch(void* const* d_in, const int* in_sizes, int n_in,
                              void* d_out, int out_size) {
    const float* hs   = (const float*)d_in[0];
    const float* cosb = (const float*)d_in[1];
    const float* sinb = (const float*)d_in[2];
    const float* Wq   = (const float*)d_in[3];
    const float* Wk   = (const float*)d_in[4];
    const float* Wv   = (const float*)d_in[5];
    const float* Wo   = (const float*)d_in[6];
    const void*  allow = d_in[7];
    float* out = (float*)d_out;

    decode_mask_kernel<<<1, 256>>>(allow);

    // Fused QKV projection
    qkv_gemm<<<dim3(24, T_SEQ / 128), 256>>>(hs, Wq, Wk, Wv);

    // RoPE (q, k in place)
    {
        int total = T_SEQ * (NH + NKV) * 32;
        rope_kernel<<<(total + 255) / 256, 256>>>(cosb, sinb);
    }

    // Pre-convert K (post-RoPE) and V for attention
    prep_k_kernel<<<(NKV * T_SEQ * HD + 255) / 256, 256>>>();
    prep_v_kernel<<<(NKV * HD * T_SEQ + 255) / 256, 256>>>();

    // MMA flash attention
    attn_mma_kernel<<<dim3(NH, NBLK), 128>>>();

    // Output projection
    out_gemm<<<dim3(EMB / 128, T_SEQ / 128), 256>>>(Wo, out);
}

// round 6
// speedup vs baseline: 3.3614x; 1.0838x over previous
#include <cuda_runtime.h>
#include <cuda_bf16.h>
#include <math.h>
#include <stdint.h>

// Problem constants (fixed by setup_inputs)
#define T_SEQ 2048
#define EMB   2048
#define NH    32
#define NKV   8
#define HD    64
#define NBLK  32
#define WIN   256
#define KVD   (NKV * HD)   // 512

// fp32 scratch
__device__ float g_q[T_SEQ * NH * HD];     // [t][h][d]
__device__ float g_k[T_SEQ * NKV * HD];    // [t][kv][d]
__device__ float g_v[T_SEQ * NKV * HD];
__device__ int   g_allow[NBLK * NBLK];

// bf16 hi/lo pre-converted operands
__device__ __nv_bfloat16 g_hsh[T_SEQ * EMB], g_hsl[T_SEQ * EMB];
__device__ __nv_bfloat16 g_wqh[EMB * EMB],  g_wql[EMB * EMB];
__device__ __nv_bfloat16 g_wkh[KVD * EMB],  g_wkl[KVD * EMB];
__device__ __nv_bfloat16 g_wvh[KVD * EMB],  g_wvl[KVD * EMB];
__device__ __nv_bfloat16 g_woh[EMB * EMB],  g_wol[EMB * EMB];
__device__ __nv_bfloat16 g_oh[T_SEQ * EMB], g_ol[T_SEQ * EMB];

// attention K/V bf16 hi/lo (K: [kv][t][d], V transposed: [kv][d][t])
__device__ __nv_bfloat16 g_kh[NKV * T_SEQ * HD], g_kl[NKV * T_SEQ * HD];
__device__ __nv_bfloat16 g_vh[NKV * HD * T_SEQ], g_vl[NKV * HD * T_SEQ];

// ---------------------------------------------------------------------------
// Decode rw_allow_blocks robustly (bool/int8 vs int32 vs float32).
// ---------------------------------------------------------------------------
__global__ void decode_mask_kernel(const void* p) {
    __shared__ int cnt0, cnt123;
    int tid = threadIdx.x;
    if (tid == 0) { cnt0 = 0; cnt123 = 0; }
    __syncthreads();
    const unsigned char* b = (const unsigned char*)p;
    int l0 = 0, l123 = 0;
    for (int i = tid; i < 1024; i += 256) {
        if (b[i]) { if ((i & 3) == 0) l0++; else l123++; }
    }
    atomicAdd(&cnt0, l0);
    atomicAdd(&cnt123, l123);
    __syncthreads();
    if (cnt123 == 0) {
        const int* a = (const int*)p;
        for (int i = tid; i < 1024; i += 256) g_allow[i] = (a[i] != 0);
    } else if (cnt0 == 0) {
        const float* a = (const float*)p;
        for (int i = tid; i < 1024; i += 256) g_allow[i] = (a[i] != 0.0f);
    } else {
        for (int i = tid; i < 1024; i += 256) g_allow[i] = (b[i] != 0);
    }
}

// ---------------------------------------------------------------------------
// Shared helpers
// ---------------------------------------------------------------------------
#define MMA_BF16(d, a0, a1, a2, a3, b0, b1)                                   \
    asm volatile(                                                             \
        "mma.sync.aligned.m16n8k16.row.col.f32.bf16.bf16.f32 "                \
        "{%0,%1,%2,%3}, {%4,%5,%6,%7}, {%8,%9}, {%0,%1,%2,%3};"               \
        : "+f"(d[0]), "+f"(d[1]), "+f"(d[2]), "+f"(d[3])                      \
        : "r"(a0), "r"(a1), "r"(a2), "r"(a3), "r"(b0), "r"(b1))

__device__ __forceinline__ void cp16(uint32_t saddr, const void* g) {
    asm volatile("cp.async.cg.shared.global [%0], [%1], 16;" :: "r"(saddr), "l"(g));
}
__device__ __forceinline__ void cp_commit() {
    asm volatile("cp.async.commit_group;" ::: "memory");
}

__device__ __forceinline__ void cvt2(float2 f, uint32_t& hi, uint32_t& lo) {
    __nv_bfloat162 h = __floats2bfloat162_rn(f.x, f.y);
    hi = *reinterpret_cast<uint32_t*>(&h);
    __nv_bfloat162 l = __floats2bfloat162_rn(f.x - __bfloat162float(h.x),
                                             f.y - __bfloat162float(h.y));
    lo = *reinterpret_cast<uint32_t*>(&l);
}

// fp32 -> bf16 hi/lo, 2 elements per thread
__global__ void cvt_hilo(const float* __restrict__ src,
                         __nv_bfloat16* __restrict__ h,
                         __nv_bfloat16* __restrict__ l, int n2) {
    int i = blockIdx.x * blockDim.x + threadIdx.x;
    if (i >= n2) return;
    float2 v = ((const float2*)src)[i];
    uint32_t hi, lo;
    cvt2(v, hi, lo);
    ((uint32_t*)h)[i] = hi;
    ((uint32_t*)l)[i] = lo;
}

// ---------------------------------------------------------------------------
// GEMM v2: C[M,N] = A[M,K] * B[N,K]^T with pre-split bf16 hi/lo operands.
// Block 128x128, BK=16, cp.async double buffer, zero conversion in hot loop.
// smem: 4 tile-pairs x 2 stages = 48KB. Row pad 24 bf16 -> conflict-free LDS.
// ---------------------------------------------------------------------------
#define TPAD 24

__device__ __forceinline__ void gemm2_core(
    const __nv_bfloat16* __restrict__ Ah, const __nv_bfloat16* __restrict__ Al,
    const __nv_bfloat16* __restrict__ Bh, const __nv_bfloat16* __restrict__ Bl,
    float* __restrict__ C, int K, int ldc, int m0, int n0)
{
    __shared__ __nv_bfloat16 sA[2][2][128][TPAD];   // [stage][h/l][row][k]
    __shared__ __nv_bfloat16 sB[2][2][128][TPAD];

    int tid  = threadIdx.x;
    int warp = tid >> 5;
    int lane = tid & 31;
    int wm = warp & 1;
    int wn = warp >> 1;
    int qr = lane >> 2;
    int qc2 = (lane & 3) * 2;

    float acc[4][4][4];
#pragma unroll
    for (int i = 0; i < 4; i++)
#pragma unroll
        for (int j = 0; j < 4; j++)
#pragma unroll
            for (int e = 0; e < 4; e++) acc[i][j][e] = 0.0f;

    // copy mapping: each thread does 4 cp16 per stage (one per tile array)
    int crow = tid >> 1;
    int cch  = (tid & 1) * 8;         // bf16 offset (16B chunk)
    const __nv_bfloat16* aH = Ah + (size_t)(m0 + crow) * K + cch;
    const __nv_bfloat16* aL = Al + (size_t)(m0 + crow) * K + cch;
    const __nv_bfloat16* bH = Bh + (size_t)(n0 + crow) * K + cch;
    const __nv_bfloat16* bL = Bl + (size_t)(n0 + crow) * K + cch;
    uint32_t dAh = (uint32_t)__cvta_generic_to_shared(&sA[0][0][crow][cch]);
    uint32_t dAl = (uint32_t)__cvta_generic_to_shared(&sA[0][1][crow][cch]);
    uint32_t dBh = (uint32_t)__cvta_generic_to_shared(&sB[0][0][crow][cch]);
    uint32_t dBl = (uint32_t)__cvta_generic_to_shared(&sB[0][1][crow][cch]);
    const uint32_t stg = 2 * 128 * TPAD * 2;   // bytes per stage

    const int NITER = K / 16;

    // prologue
    cp16(dAh, aH); cp16(dAl, aL); cp16(dBh, bH); cp16(dBl, bL);
    cp_commit();

    for (int it = 0; it < NITER; it++) {
        if (it + 1 < NITER) {
            int k0 = (it + 1) * 16;
            uint32_t so = ((it + 1) & 1) * stg;
            cp16(dAh + so, aH + k0); cp16(dAl + so, aL + k0);
            cp16(dBh + so, bH + k0); cp16(dBl + so, bL + k0);
            cp_commit();
            asm volatile("cp.async.wait_group 1;" ::: "memory");
        } else {
            asm volatile("cp.async.wait_group 0;" ::: "memory");
        }
        __syncthreads();

        int st = it & 1;
        uint32_t ah[4][4], al[4][4];
#pragma unroll
        for (int mi = 0; mi < 4; mi++) {
            int r = wm * 64 + mi * 16 + qr;
            ah[mi][0] = *(const uint32_t*)&sA[st][0][r][qc2];
            ah[mi][1] = *(const uint32_t*)&sA[st][0][r + 8][qc2];
            ah[mi][2] = *(const uint32_t*)&sA[st][0][r][qc2 + 8];
            ah[mi][3] = *(const uint32_t*)&sA[st][0][r + 8][qc2 + 8];
            al[mi][0] = *(const uint32_t*)&sA[st][1][r][qc2];
            al[mi][1] = *(const uint32_t*)&sA[st][1][r + 8][qc2];
            al[mi][2] = *(const uint32_t*)&sA[st][1][r][qc2 + 8];
            al[mi][3] = *(const uint32_t*)&sA[st][1][r + 8][qc2 + 8];
        }
#pragma unroll
        for (int ni = 0; ni < 4; ni++) {
            int n = wn * 32 + ni * 8 + qr;
            uint32_t bh0 = *(const uint32_t*)&sB[st][0][n][qc2];
            uint32_t bh1 = *(const uint32_t*)&sB[st][0][n][qc2 + 8];
            uint32_t bl0 = *(const uint32_t*)&sB[st][1][n][qc2];
            uint32_t bl1 = *(const uint32_t*)&sB[st][1][n][qc2 + 8];
#pragma unroll
            for (int mi = 0; mi < 4; mi++) {
                MMA_BF16(acc[mi][ni], ah[mi][0], ah[mi][1], ah[mi][2], ah[mi][3], bh0, bh1);
                MMA_BF16(acc[mi][ni], ah[mi][0], ah[mi][1], ah[mi][2], ah[mi][3], bl0, bl1);
                MMA_BF16(acc[mi][ni], al[mi][0], al[mi][1], al[mi][2], al[mi][3], bh0, bh1);
            }
        }
        __syncthreads();
    }

    // epilogue
#pragma unroll
    for (int mi = 0; mi < 4; mi++) {
#pragma unroll
        for (int ni = 0; ni < 4; ni++) {
            int r = m0 + wm * 64 + mi * 16 + qr;
            int cidx = n0 + wn * 32 + ni * 8 + qc2;
            *(float2*)&C[(size_t)r * ldc + cidx] =
                make_float2(acc[mi][ni][0], acc[mi][ni][1]);
            *(float2*)&C[(size_t)(r + 8) * ldc + cidx] =
                make_float2(acc[mi][ni][2], acc[mi][ni][3]);
        }
    }
}

__global__ __launch_bounds__(256)
void qkv_gemm() {
    int bx = blockIdx.x;
    int m0 = blockIdx.y * 128;
    if (bx < 16)
        gemm2_core(g_hsh, g_hsl, g_wqh, g_wql, g_q, EMB, EMB, m0, bx * 128);
    else if (bx < 20)
        gemm2_core(g_hsh, g_hsl, g_wkh, g_wkl, g_k, EMB, KVD, m0, (bx - 16) * 128);
    else
        gemm2_core(g_hsh, g_hsl, g_wvh, g_wvl, g_v, EMB, KVD, m0, (bx - 20) * 128);
}

__global__ __launch_bounds__(256)
void out_gemm(float* __restrict__ out) {
    gemm2_core(g_oh, g_ol, g_woh, g_wol, out, EMB, EMB,
               blockIdx.y * 128, blockIdx.x * 128);
}

// ---------------------------------------------------------------------------
// RoPE applied in-place to q and k.
// ---------------------------------------------------------------------------
__global__ void rope_kernel(const float* __restrict__ cosb, const float* __restrict__ sinb) {
    int idx = blockIdx.x * blockDim.x + threadIdx.x;
    const int total = T_SEQ * (NH + NKV) * 32;
    if (idx >= total) return;
    int d = idx & 31;
    int rest = idx >> 5;
    int head = rest % (NH + NKV);
    int t = rest / (NH + NKV);
    float c0 = cosb[t * HD + d];
    float s0 = sinb[t * HD + d];
    float c1 = cosb[t * HD + d + 32];
    float s1 = sinb[t * HD + d + 32];
    float* base = (head < NH) ? (g_q + ((size_t)t * NH + head) * HD)
                              : (g_k + ((size_t)t * NKV + (head - NH)) * HD);
    float x0 = base[d];
    float x1 = base[d + 32];
    base[d]      = x0 * c0 - x1 * s0;
    base[d + 32] = x1 * c1 + x0 * s1;
}

// ---------------------------------------------------------------------------
// Prep: K (post-RoPE) -> bf16 hi/lo [kv][t][d]; V -> transposed [kv][d][t].
// ---------------------------------------------------------------------------
__global__ void prep_k_kernel() {
    int o = blockIdx.x * blockDim.x + threadIdx.x;
    if (o >= NKV * T_SEQ * HD) return;
    int d  = o & 63;
    int t  = (o >> 6) & (T_SEQ - 1);
    int kv = o >> 17;
    float v = g_k[((size_t)t * NKV + kv) * HD + d];
    __nv_bfloat16 h = __float2bfloat16(v);
    g_kh[o] = h;
    g_kl[o] = __float2bfloat16(v - __bfloat162float(h));
}

__global__ void prep_v_kernel() {
    int o = blockIdx.x * blockDim.x + threadIdx.x;
    if (o >= NKV * HD * T_SEQ) return;
    int t  = o & (T_SEQ - 1);
    int d  = (o >> 11) & 63;
    int kv = o >> 17;
    float v = g_v[((size_t)t * NKV + kv) * HD + d];
    __nv_bfloat16 h = __float2bfloat16(v);
    g_vh[o] = h;
    g_vl[o] = __float2bfloat16(v - __bfloat162float(h));
}

// ---------------------------------------------------------------------------
// MMA flash attention (unchanged core; output written as bf16 hi/lo).
// ---------------------------------------------------------------------------
#define TSTR 72

__global__ __launch_bounds__(128)
void attn_mma_kernel() {
    __shared__ __align__(16) __nv_bfloat16 sT[4][64][TSTR];

    int h  = blockIdx.x;
    int qb = blockIdx.y;
    int kv = h >> 2;
    int tid  = threadIdx.x;
    int w    = tid >> 5;
    int lane = tid & 31;
    int qr   = lane >> 2;
    int qc2  = (lane & 3) * 2;
    int rowA = w * 16 + qr;

    // stage Q (fp32, pre-scaled), build A-frags, release smem
    float* sQ = (float*)&sT[0][0][0];
    for (int i = tid; i < 64 * 16; i += 128) {
        int row = i >> 4;
        int c4  = (i & 15) * 4;
        float4 v = *(const float4*)&g_q[(((size_t)qb * 64 + row) * NH + h) * HD + c4];
        v.x *= 0.125f; v.y *= 0.125f; v.z *= 0.125f; v.w *= 0.125f;
        *(float4*)&sQ[row * 68 + c4] = v;
    }
    __syncthreads();

    uint32_t qh[4][4], ql[4][4];
#pragma unroll
    for (int kc = 0; kc < 4; kc++) {
        int k = kc * 16 + qc2;
        cvt2(*(const float2*)&sQ[rowA * 68 + k],           qh[kc][0], ql[kc][0]);
        cvt2(*(const float2*)&sQ[(rowA + 8) * 68 + k],     qh[kc][1], ql[kc][1]);
        cvt2(*(const float2*)&sQ[rowA * 68 + k + 8],       qh[kc][2], ql[kc][2]);
        cvt2(*(const float2*)&sQ[(rowA + 8) * 68 + k + 8], qh[kc][3], ql[kc][3]);
    }
    __syncthreads();

    float m0 = -1e30f, m1 = -1e30f, l0 = 0.0f, l1 = 0.0f;
    float o[8][4];
#pragma unroll
    for (int ni = 0; ni < 8; ni++)
#pragma unroll
        for (int e = 0; e < 4; e++) o[ni][e] = 0.0f;

    for (int kb = 0; kb < NBLK; kb++) {
        int ba = g_allow[qb * NBLK + kb];
        bool win_possible = (kb < 4) || (kb <= qb && kb + 4 >= qb);
        if (!ba && !win_possible) continue;

#pragma unroll
        for (int t = 0; t < 16; t++) {
            int id   = t * 128 + tid;
            int tile = id >> 9;
            int row  = (id >> 3) & 63;
            int ch   = id & 7;
            const __nv_bfloat16* src;
            if (tile == 0)
                src = g_kh + (((size_t)kv * T_SEQ + kb * 64 + row) * HD + ch * 8);
            else if (tile == 1)
                src = g_kl + (((size_t)kv * T_SEQ + kb * 64 + row) * HD + ch * 8);
            else if (tile == 2)
                src = g_vh + (((size_t)kv * HD + row) * T_SEQ + kb * 64 + ch * 8);
            else
                src = g_vl + (((size_t)kv * HD + row) * T_SEQ + kb * 64 + ch * 8);
            cp16((uint32_t)__cvta_generic_to_shared(&sT[tile][row][ch * 8]), src);
        }
        cp_commit();
        asm volatile("cp.async.wait_group 0;" ::: "memory");
        __syncthreads();

        float s[8][4];
#pragma unroll
        for (int ni = 0; ni < 8; ni++) {
#pragma unroll
            for (int e = 0; e < 4; e++) s[ni][e] = 0.0f;
            int n = ni * 8 + qr;
#pragma unroll
            for (int kc = 0; kc < 4; kc++) {
                int kcol = kc * 16 + qc2;
                uint32_t bh0 = *(const uint32_t*)&sT[0][n][kcol];
                uint32_t bh1 = *(const uint32_t*)&sT[0][n][kcol + 8];
                uint32_t bl0 = *(const uint32_t*)&sT[1][n][kcol];
                uint32_t bl1 = *(const uint32_t*)&sT[1][n][kcol + 8];
                MMA_BF16(s[ni], qh[kc][0], qh[kc][1], qh[kc][2], qh[kc][3], bh0, bh1);
                MMA_BF16(s[ni], qh[kc][0], qh[kc][1], qh[kc][2], qh[kc][3], bl0, bl1);
                MMA_BF16(s[ni], ql[kc][0], ql[kc][1], ql[kc][2], ql[kc][3], bh0, bh1);
            }
        }

        int qi0 = qb * 64 + rowA;
        int qi1 = qi0 + 8;
#pragma unroll
        for (int ni = 0; ni < 8; ni++) {
            int col = kb * 64 + ni * 8 + qc2;
#pragma unroll
            for (int e = 0; e < 4; e++) {
                int kj = col + (e & 1);
                int qi = (e < 2) ? qi0 : qi1;
                bool ok = ba || (kj < WIN) || (kj <= qi && kj + (WIN - 1) >= qi);
                if (!ok) s[ni][e] = -1e30f;
            }
        }

        float mb0 = -1e30f, mb1 = -1e30f;
#pragma unroll
        for (int ni = 0; ni < 8; ni++) {
            mb0 = fmaxf(mb0, fmaxf(s[ni][0], s[ni][1]));
            mb1 = fmaxf(mb1, fmaxf(s[ni][2], s[ni][3]));
        }
        mb0 = fmaxf(mb0, __shfl_xor_sync(0xFFFFFFFF, mb0, 1));
        mb0 = fmaxf(mb0, __shfl_xor_sync(0xFFFFFFFF, mb0, 2));
        mb1 = fmaxf(mb1, __shfl_xor_sync(0xFFFFFFFF, mb1, 1));
        mb1 = fmaxf(mb1, __shfl_xor_sync(0xFFFFFFFF, mb1, 2));

        float mn0 = fmaxf(m0, mb0), mn1 = fmaxf(m1, mb1);
        float sc0 = __expf(m0 - mn0), sc1 = __expf(m1 - mn1);
        m0 = mn0; m1 = mn1;
        l0 *= sc0; l1 *= sc1;
#pragma unroll
        for (int ni = 0; ni < 8; ni++) {
            o[ni][0] *= sc0; o[ni][1] *= sc0;
            o[ni][2] *= sc1; o[ni][3] *= sc1;
        }

#pragma unroll
        for (int ni = 0; ni < 8; ni++) {
            s[ni][0] = __expf(s[ni][0] - m0);
            s[ni][1] = __expf(s[ni][1] - m0);
            s[ni][2] = __expf(s[ni][2] - m1);
            s[ni][3] = __expf(s[ni][3] - m1);
            l0 += s[ni][0] + s[ni][1];
            l1 += s[ni][2] + s[ni][3];
        }

#pragma unroll
        for (int kc = 0; kc < 4; kc++) {
            uint32_t ah[4], al[4];
            cvt2(make_float2(s[2 * kc][0],     s[2 * kc][1]),     ah[0], al[0]);
            cvt2(make_float2(s[2 * kc][2],     s[2 * kc][3]),     ah[1], al[1]);
            cvt2(make_float2(s[2 * kc + 1][0], s[2 * kc + 1][1]), ah[2], al[2]);
            cvt2(make_float2(s[2 * kc + 1][2], s[2 * kc + 1][3]), ah[3], al[3]);
#pragma unroll
            for (int ni = 0; ni < 8; ni++) {
                int n = ni * 8 + qr;
                int kcol = kc * 16 + qc2;
                uint32_t bh0 = *(const uint32_t*)&sT[2][n][kcol];
                uint32_t bh1 = *(const uint32_t*)&sT[2][n][kcol + 8];
                uint32_t bl0 = *(const uint32_t*)&sT[3][n][kcol];
                uint32_t bl1 = *(const uint32_t*)&sT[3][n][kcol + 8];
                MMA_BF16(o[ni], ah[0], ah[1], ah[2], ah[3], bh0, bh1);
                MMA_BF16(o[ni], ah[0], ah[1], ah[2], ah[3], bl0, bl1);
                MMA_BF16(o[ni], al[0], al[1], al[2], al[3], bh0, bh1);
            }
        }
        __syncthreads();
    }

    // finalize: reduce l, normalize, write bf16 hi/lo directly
    l0 += __shfl_xor_sync(0xFFFFFFFF, l0, 1);
    l0 += __shfl_xor_sync(0xFFFFFFFF, l0, 2);
    l1 += __shfl_xor_sync(0xFFFFFFFF, l1, 1);
    l1 += __shfl_xor_sync(0xFFFFFFFF, l1, 2);
    float inv0 = 1.0f / l0, inv1 = 1.0f / l1;

    int qi0 = qb * 64 + rowA;
#pragma unroll
    for (int ni = 0; ni < 8; ni++) {
        int d = ni * 8 + qc2;
        uint32_t hi, lo;
        cvt2(make_float2(o[ni][0] * inv0, o[ni][1] * inv0), hi, lo);
        int idx0 = ((size_t)qi0 * EMB + h * HD + d) >> 1;
        ((uint32_t*)g_oh)[idx0] = hi;
        ((uint32_t*)g_ol)[idx0] = lo;
        cvt2(make_float2(o[ni][2] * inv1, o[ni][3] * inv1), hi, lo);
        int idx1 = ((size_t)(qi0 + 8) * EMB + h * HD + d) >> 1;
        ((uint32_t*)g_oh)[idx1] = hi;
        ((uint32_t*)g_ol)[idx1] = lo;
    }
}

// ---------------------------------------------------------------------------
extern "C" void kernel_launch(void* const* d_in, const int* in_sizes, int n_in,
                              void* d_out, int out_size) {
    const float* hs   = (const float*)d_in[0];
    const float* cosb = (const float*)d_in[1];
    const float* sinb = (const float*)d_in[2];
    const float* Wq   = (const float*)d_in[3];
    const float* Wk   = (const float*)d_in[4];
    const float* Wv   = (const float*)d_in[5];
    const float* Wo   = (const float*)d_in[6];
    const void*  allow = d_in[7];
    float* out = (float*)d_out;

    __nv_bfloat16 *hsh, *hsl, *wqh, *wql, *wkh, *wkl, *wvh, *wvl, *woh, *wol;
    cudaGetSymbolAddress((void**)&hsh, g_hsh);
    cudaGetSymbolAddress((void**)&hsl, g_hsl);
    cudaGetSymbolAddress((void**)&wqh, g_wqh);
    cudaGetSymbolAddress((void**)&wql, g_wql);
    cudaGetSymbolAddress((void**)&wkh, g_wkh);
    cudaGetSymbolAddress((void**)&wkl, g_wkl);
    cudaGetSymbolAddress((void**)&wvh, g_wvh);
    cudaGetSymbolAddress((void**)&wvl, g_wvl);
    cudaGetSymbolAddress((void**)&woh, g_woh);
    cudaGetSymbolAddress((void**)&wol, g_wol);

    decode_mask_kernel<<<1, 256>>>(allow);

    // one-time bf16 hi/lo conversion of GEMM operands
    {
        int n2 = T_SEQ * EMB / 2;
        cvt_hilo<<<(n2 + 255) / 256, 256>>>(hs, hsh, hsl, n2);
        n2 = EMB * EMB / 2;
        cvt_hilo<<<(n2 + 255) / 256, 256>>>(Wq, wqh, wql, n2);
        cvt_hilo<<<(n2 + 255) / 256, 256>>>(Wo, woh, wol, n2);
        n2 = KVD * EMB / 2;
        cvt_hilo<<<(n2 + 255) / 256, 256>>>(Wk, wkh, wkl, n2);
        cvt_hilo<<<(n2 + 255) / 256, 256>>>(Wv, wvh, wvl, n2);
    }

    // Fused QKV projection
    qkv_gemm<<<dim3(24, T_SEQ / 128), 256>>>();

    // RoPE (q, k in place)
    {
        int total = T_SEQ * (NH + NKV) * 32;
        rope_kernel<<<(total + 255) / 256, 256>>>(cosb, sinb);
    }

    // Pre-convert K (post-RoPE) and V for attention
    prep_k_kernel<<<(NKV * T_SEQ * HD + 255) / 256, 256>>>();
    prep_v_kernel<<<(NKV * HD * T_SEQ + 255) / 256, 256>>>();

    // MMA flash attention (writes bf16 hi/lo output)
    attn_mma_kernel<<<dim3(NH, NBLK), 128>>>();

    // Output projection
    out_gemm<<<dim3(EMB / 128, T_SEQ / 128), 256>>>(out);
}

// round 7
// speedup vs baseline: 3.4901x; 1.0383x over previous
#include <cuda_runtime.h>
#include <cuda_bf16.h>
#include <math.h>
#include <stdint.h>

// Problem constants (fixed by setup_inputs)
#define T_SEQ 2048
#define EMB   2048
#define NH    32
#define NKV   8
#define HD    64
#define NBLK  32
#define WIN   256
#define KVD   (NKV * HD)   // 512

// fp32 scratch
__device__ float g_q[T_SEQ * NH * HD];     // [t][h][d]
__device__ float g_k[T_SEQ * NKV * HD];    // [t][kv][d]
__device__ float g_v[T_SEQ * NKV * HD];
__device__ int   g_allow[NBLK * NBLK];

// bf16 hi/lo pre-converted operands
__device__ __nv_bfloat16 g_hsh[T_SEQ * EMB], g_hsl[T_SEQ * EMB];
__device__ __nv_bfloat16 g_wqh[EMB * EMB],  g_wql[EMB * EMB];
__device__ __nv_bfloat16 g_wkh[KVD * EMB],  g_wkl[KVD * EMB];
__device__ __nv_bfloat16 g_wvh[KVD * EMB],  g_wvl[KVD * EMB];
__device__ __nv_bfloat16 g_woh[EMB * EMB],  g_wol[EMB * EMB];
__device__ __nv_bfloat16 g_oh[T_SEQ * EMB], g_ol[T_SEQ * EMB];

// attention K/V bf16 hi/lo (K: [kv][t][d], V transposed: [kv][d][t])
__device__ __nv_bfloat16 g_kh[NKV * T_SEQ * HD], g_kl[NKV * T_SEQ * HD];
__device__ __nv_bfloat16 g_vh[NKV * HD * T_SEQ], g_vl[NKV * HD * T_SEQ];

// ---------------------------------------------------------------------------
// Decode rw_allow_blocks robustly (bool/int8 vs int32 vs float32).
// ---------------------------------------------------------------------------
__global__ void decode_mask_kernel(const void* p) {
    __shared__ int cnt0, cnt123;
    int tid = threadIdx.x;
    if (tid == 0) { cnt0 = 0; cnt123 = 0; }
    __syncthreads();
    const unsigned char* b = (const unsigned char*)p;
    int l0 = 0, l123 = 0;
    for (int i = tid; i < 1024; i += 256) {
        if (b[i]) { if ((i & 3) == 0) l0++; else l123++; }
    }
    atomicAdd(&cnt0, l0);
    atomicAdd(&cnt123, l123);
    __syncthreads();
    if (cnt123 == 0) {
        const int* a = (const int*)p;
        for (int i = tid; i < 1024; i += 256) g_allow[i] = (a[i] != 0);
    } else if (cnt0 == 0) {
        const float* a = (const float*)p;
        for (int i = tid; i < 1024; i += 256) g_allow[i] = (a[i] != 0.0f);
    } else {
        for (int i = tid; i < 1024; i += 256) g_allow[i] = (b[i] != 0);
    }
}

// ---------------------------------------------------------------------------
// Shared helpers
// ---------------------------------------------------------------------------
#define MMA_BF16(d, a0, a1, a2, a3, b0, b1)                                   \
    asm volatile(                                                             \
        "mma.sync.aligned.m16n8k16.row.col.f32.bf16.bf16.f32 "                \
        "{%0,%1,%2,%3}, {%4,%5,%6,%7}, {%8,%9}, {%0,%1,%2,%3};"               \
        : "+f"(d[0]), "+f"(d[1]), "+f"(d[2]), "+f"(d[3])                      \
        : "r"(a0), "r"(a1), "r"(a2), "r"(a3), "r"(b0), "r"(b1))

#define LDSM_X4(R0, R1, R2, R3, ADDR)                                         \
    asm volatile("ldmatrix.sync.aligned.m8n8.x4.shared.b16 {%0,%1,%2,%3}, [%4];" \
        : "=r"(R0), "=r"(R1), "=r"(R2), "=r"(R3) : "r"(ADDR))

#define LDSM_X2(R0, R1, ADDR)                                                 \
    asm volatile("ldmatrix.sync.aligned.m8n8.x2.shared.b16 {%0,%1}, [%2];"    \
        : "=r"(R0), "=r"(R1) : "r"(ADDR))

__device__ __forceinline__ void cp16(uint32_t saddr, const void* g) {
    asm volatile("cp.async.cg.shared.global [%0], [%1], 16;" :: "r"(saddr), "l"(g));
}
__device__ __forceinline__ void cp_commit() {
    asm volatile("cp.async.commit_group;" ::: "memory");
}

__device__ __forceinline__ void cvt2(float2 f, uint32_t& hi, uint32_t& lo) {
    __nv_bfloat162 h = __floats2bfloat162_rn(f.x, f.y);
    hi = *reinterpret_cast<uint32_t*>(&h);
    __nv_bfloat162 l = __floats2bfloat162_rn(f.x - __bfloat162float(h.x),
                                             f.y - __bfloat162float(h.y));
    lo = *reinterpret_cast<uint32_t*>(&l);
}

// fp32 -> bf16 hi/lo, 2 elements per thread
__global__ void cvt_hilo(const float* __restrict__ src,
                         __nv_bfloat16* __restrict__ h,
                         __nv_bfloat16* __restrict__ l, int n2) {
    int i = blockIdx.x * blockDim.x + threadIdx.x;
    if (i >= n2) return;
    float2 v = ((const float2*)src)[i];
    uint32_t hi, lo;
    cvt2(v, hi, lo);
    ((uint32_t*)h)[i] = hi;
    ((uint32_t*)l)[i] = lo;
}

// ---------------------------------------------------------------------------
// GEMM v3: pre-split bf16 hi/lo operands + ldmatrix fragment loads.
// Block 128x128, BK=16, cp.async double buffer, 2 CTAs/SM target.
// ---------------------------------------------------------------------------
#define TPAD 24

__device__ __forceinline__ void gemm2_core(
    const __nv_bfloat16* __restrict__ Ah, const __nv_bfloat16* __restrict__ Al,
    const __nv_bfloat16* __restrict__ Bh, const __nv_bfloat16* __restrict__ Bl,
    float* __restrict__ C, int K, int ldc, int m0, int n0)
{
    __shared__ __nv_bfloat16 sA[2][2][128][TPAD];   // [stage][h/l][row][k]
    __shared__ __nv_bfloat16 sB[2][2][128][TPAD];

    int tid  = threadIdx.x;
    int warp = tid >> 5;
    int lane = tid & 31;
    int wm = warp & 1;
    int wn = warp >> 1;
    int qr = lane >> 2;
    int qc2 = (lane & 3) * 2;

    float acc[4][4][4];
#pragma unroll
    for (int i = 0; i < 4; i++)
#pragma unroll
        for (int j = 0; j < 4; j++)
#pragma unroll
            for (int e = 0; e < 4; e++) acc[i][j][e] = 0.0f;

    // copy mapping: each thread does 4 cp16 per stage
    int crow = tid >> 1;
    int cch  = (tid & 1) * 8;
    const __nv_bfloat16* aH = Ah + (size_t)(m0 + crow) * K + cch;
    const __nv_bfloat16* aL = Al + (size_t)(m0 + crow) * K + cch;
    const __nv_bfloat16* bH = Bh + (size_t)(n0 + crow) * K + cch;
    const __nv_bfloat16* bL = Bl + (size_t)(n0 + crow) * K + cch;
    uint32_t dAh = (uint32_t)__cvta_generic_to_shared(&sA[0][0][crow][cch]);
    uint32_t dAl = (uint32_t)__cvta_generic_to_shared(&sA[0][1][crow][cch]);
    uint32_t dBh = (uint32_t)__cvta_generic_to_shared(&sB[0][0][crow][cch]);
    uint32_t dBl = (uint32_t)__cvta_generic_to_shared(&sB[0][1][crow][cch]);
    const uint32_t stg = 2 * 128 * TPAD * 2;   // bytes per stage

    // ldmatrix source addresses (stage 0)
    int lrow = wm * 64 + (lane & 7) + ((lane >> 3) & 1) * 8;
    int lcol = ((lane >> 4) & 1) * 8;
    uint32_t aFH = (uint32_t)__cvta_generic_to_shared(&sA[0][0][lrow][lcol]);
    uint32_t aFL = (uint32_t)__cvta_generic_to_shared(&sA[0][1][lrow][lcol]);
    int brow = wn * 32 + (lane & 7);
    int bcol = ((lane >> 3) & 1) * 8;      // lanes 0..15 matter for x2
    uint32_t bFH = (uint32_t)__cvta_generic_to_shared(&sB[0][0][brow][bcol]);
    uint32_t bFL = (uint32_t)__cvta_generic_to_shared(&sB[0][1][brow][bcol]);

    const int NITER = K / 16;

    cp16(dAh, aH); cp16(dAl, aL); cp16(dBh, bH); cp16(dBl, bL);
    cp_commit();

    for (int it = 0; it < NITER; it++) {
        if (it + 1 < NITER) {
            int k0 = (it + 1) * 16;
            uint32_t so = ((it + 1) & 1) * stg;
            cp16(dAh + so, aH + k0); cp16(dAl + so, aL + k0);
            cp16(dBh + so, bH + k0); cp16(dBl + so, bL + k0);
            cp_commit();
            asm volatile("cp.async.wait_group 1;" ::: "memory");
        } else {
            asm volatile("cp.async.wait_group 0;" ::: "memory");
        }
        __syncthreads();

        uint32_t so = (it & 1) * stg;
        uint32_t ah[4][4], al[4][4];
#pragma unroll
        for (int mi = 0; mi < 4; mi++) {
            uint32_t off = so + mi * (16 * TPAD * 2);
            LDSM_X4(ah[mi][0], ah[mi][1], ah[mi][2], ah[mi][3], aFH + off);
            LDSM_X4(al[mi][0], al[mi][1], al[mi][2], al[mi][3], aFL + off);
        }
#pragma unroll
        for (int ni = 0; ni < 4; ni++) {
            uint32_t off = so + ni * (8 * TPAD * 2);
            uint32_t bh0, bh1, bl0, bl1;
            LDSM_X2(bh0, bh1, bFH + off);
            LDSM_X2(bl0, bl1, bFL + off);
#pragma unroll
            for (int mi = 0; mi < 4; mi++) {
                MMA_BF16(acc[mi][ni], ah[mi][0], ah[mi][1], ah[mi][2], ah[mi][3], bh0, bh1);
                MMA_BF16(acc[mi][ni], ah[mi][0], ah[mi][1], ah[mi][2], ah[mi][3], bl0, bl1);
                MMA_BF16(acc[mi][ni], al[mi][0], al[mi][1], al[mi][2], al[mi][3], bh0, bh1);
            }
        }
        __syncthreads();
    }

    // epilogue
#pragma unroll
    for (int mi = 0; mi < 4; mi++) {
#pragma unroll
        for (int ni = 0; ni < 4; ni++) {
            int r = m0 + wm * 64 + mi * 16 + qr;
            int cidx = n0 + wn * 32 + ni * 8 + qc2;
            *(float2*)&C[(size_t)r * ldc + cidx] =
                make_float2(acc[mi][ni][0], acc[mi][ni][1]);
            *(float2*)&C[(size_t)(r + 8) * ldc + cidx] =
                make_float2(acc[mi][ni][2], acc[mi][ni][3]);
        }
    }
}

__global__ __launch_bounds__(256, 2)
void qkv_gemm() {
    int bx = blockIdx.x;
    int m0 = blockIdx.y * 128;
    if (bx < 16)
        gemm2_core(g_hsh, g_hsl, g_wqh, g_wql, g_q, EMB, EMB, m0, bx * 128);
    else if (bx < 20)
        gemm2_core(g_hsh, g_hsl, g_wkh, g_wkl, g_k, EMB, KVD, m0, (bx - 16) * 128);
    else
        gemm2_core(g_hsh, g_hsl, g_wvh, g_wvl, g_v, EMB, KVD, m0, (bx - 20) * 128);
}

__global__ __launch_bounds__(256, 2)
void out_gemm(float* __restrict__ out) {
    gemm2_core(g_oh, g_ol, g_woh, g_wol, out, EMB, EMB,
               blockIdx.y * 128, blockIdx.x * 128);
}

// ---------------------------------------------------------------------------
// RoPE applied in-place to q and k.
// ---------------------------------------------------------------------------
__global__ void rope_kernel(const float* __restrict__ cosb, const float* __restrict__ sinb) {
    int idx = blockIdx.x * blockDim.x + threadIdx.x;
    const int total = T_SEQ * (NH + NKV) * 32;
    if (idx >= total) return;
    int d = idx & 31;
    int rest = idx >> 5;
    int head = rest % (NH + NKV);
    int t = rest / (NH + NKV);
    float c0 = cosb[t * HD + d];
    float s0 = sinb[t * HD + d];
    float c1 = cosb[t * HD + d + 32];
    float s1 = sinb[t * HD + d + 32];
    float* base = (head < NH) ? (g_q + ((size_t)t * NH + head) * HD)
                              : (g_k + ((size_t)t * NKV + (head - NH)) * HD);
    float x0 = base[d];
    float x1 = base[d + 32];
    base[d]      = x0 * c0 - x1 * s0;
    base[d + 32] = x1 * c1 + x0 * s1;
}

// ---------------------------------------------------------------------------
// Prep: K (post-RoPE) -> bf16 hi/lo [kv][t][d]; V -> transposed [kv][d][t].
// ---------------------------------------------------------------------------
__global__ void prep_k_kernel() {
    int o = blockIdx.x * blockDim.x + threadIdx.x;
    if (o >= NKV * T_SEQ * HD) return;
    int d  = o & 63;
    int t  = (o >> 6) & (T_SEQ - 1);
    int kv = o >> 17;
    float v = g_k[((size_t)t * NKV + kv) * HD + d];
    __nv_bfloat16 h = __float2bfloat16(v);
    g_kh[o] = h;
    g_kl[o] = __float2bfloat16(v - __bfloat162float(h));
}

__global__ void prep_v_kernel() {
    int o = blockIdx.x * blockDim.x + threadIdx.x;
    if (o >= NKV * HD * T_SEQ) return;
    int t  = o & (T_SEQ - 1);
    int d  = (o >> 11) & 63;
    int kv = o >> 17;
    float v = g_v[((size_t)t * NKV + kv) * HD + d];
    __nv_bfloat16 h = __float2bfloat16(v);
    g_vh[o] = h;
    g_vl[o] = __float2bfloat16(v - __bfloat162float(h));
}

// ---------------------------------------------------------------------------
// MMA flash attention with double-buffered kb tiles (dynamic smem, 2 stages).
// Stage layout: 4 tiles (Kh,Kl,Vh,Vl) x 64 rows x TSTR bf16.
// ---------------------------------------------------------------------------
#define TSTR 72
#define ATT_TILE   (64 * TSTR)          // bf16 elems per tile
#define ATT_STAGE  (4 * ATT_TILE)       // bf16 elems per stage
#define ATT_SMEM   (2 * ATT_STAGE * 2)  // bytes

extern __shared__ __nv_bfloat16 att_dsm[];

__device__ __forceinline__ void att_issue_loads(int stage, int kb, int kv, int tid) {
    uint32_t base = (uint32_t)__cvta_generic_to_shared(att_dsm + stage * ATT_STAGE);
#pragma unroll
    for (int t = 0; t < 16; t++) {
        int id   = t * 128 + tid;
        int tile = id >> 9;
        int row  = (id >> 3) & 63;
        int ch   = id & 7;
        const __nv_bfloat16* src;
        if (tile == 0)
            src = g_kh + (((size_t)kv * T_SEQ + kb * 64 + row) * HD + ch * 8);
        else if (tile == 1)
            src = g_kl + (((size_t)kv * T_SEQ + kb * 64 + row) * HD + ch * 8);
        else if (tile == 2)
            src = g_vh + (((size_t)kv * HD + row) * T_SEQ + kb * 64 + ch * 8);
        else
            src = g_vl + (((size_t)kv * HD + row) * T_SEQ + kb * 64 + ch * 8);
        cp16(base + (tile * ATT_TILE + row * TSTR + ch * 8) * 2, src);
    }
    cp_commit();
}

__global__ __launch_bounds__(128)
void attn_mma_kernel() {
    int h  = blockIdx.x;
    int qb = blockIdx.y;
    int kv = h >> 2;
    int tid  = threadIdx.x;
    int w    = tid >> 5;
    int lane = tid & 31;
    int qr   = lane >> 2;
    int qc2  = (lane & 3) * 2;
    int rowA = w * 16 + qr;

    // stage Q (fp32, pre-scaled) in stage-0 region, build A-frags, release
    float* sQ = (float*)att_dsm;
    for (int i = tid; i < 64 * 16; i += 128) {
        int row = i >> 4;
        int c4  = (i & 15) * 4;
        float4 v = *(const float4*)&g_q[(((size_t)qb * 64 + row) * NH + h) * HD + c4];
        v.x *= 0.125f; v.y *= 0.125f; v.z *= 0.125f; v.w *= 0.125f;
        *(float4*)&sQ[row * 68 + c4] = v;
    }
    __syncthreads();

    uint32_t qh[4][4], ql[4][4];
#pragma unroll
    for (int kc = 0; kc < 4; kc++) {
        int k = kc * 16 + qc2;
        cvt2(*(const float2*)&sQ[rowA * 68 + k],           qh[kc][0], ql[kc][0]);
        cvt2(*(const float2*)&sQ[(rowA + 8) * 68 + k],     qh[kc][1], ql[kc][1]);
        cvt2(*(const float2*)&sQ[rowA * 68 + k + 8],       qh[kc][2], ql[kc][2]);
        cvt2(*(const float2*)&sQ[(rowA + 8) * 68 + k + 8], qh[kc][3], ql[kc][3]);
    }
    __syncthreads();

    float m0 = -1e30f, m1 = -1e30f, l0 = 0.0f, l1 = 0.0f;
    float o[8][4];
#pragma unroll
    for (int ni = 0; ni < 8; ni++)
#pragma unroll
        for (int e = 0; e < 4; e++) o[ni][e] = 0.0f;

    // kb = 0 is always live (kb < 4 window rule)
    int cur = 0, stage = 0;
    att_issue_loads(0, 0, kv, tid);

    while (cur < NBLK) {
        // find next live block, prefetch it into the other stage
        int nxt = cur + 1;
        while (nxt < NBLK) {
            if (g_allow[qb * NBLK + nxt] || (nxt < 4) ||
                (nxt <= qb && nxt + 4 >= qb)) break;
            nxt++;
        }
        if (nxt < NBLK) {
            att_issue_loads(stage ^ 1, nxt, kv, tid);
            asm volatile("cp.async.wait_group 1;" ::: "memory");
        } else {
            asm volatile("cp.async.wait_group 0;" ::: "memory");
        }
        __syncthreads();

        int kb = cur;
        int ba = g_allow[qb * NBLK + kb];
        const __nv_bfloat16* sKh = att_dsm + stage * ATT_STAGE;
        const __nv_bfloat16* sKl = sKh + ATT_TILE;
        const __nv_bfloat16* sVh = sKl + ATT_TILE;
        const __nv_bfloat16* sVl = sVh + ATT_TILE;

        // ---- S = Q K^T ----
        float s[8][4];
#pragma unroll
        for (int ni = 0; ni < 8; ni++) {
#pragma unroll
            for (int e = 0; e < 4; e++) s[ni][e] = 0.0f;
            int n = ni * 8 + qr;
#pragma unroll
            for (int kc = 0; kc < 4; kc++) {
                int kcol = kc * 16 + qc2;
                uint32_t bh0 = *(const uint32_t*)&sKh[n * TSTR + kcol];
                uint32_t bh1 = *(const uint32_t*)&sKh[n * TSTR + kcol + 8];
                uint32_t bl0 = *(const uint32_t*)&sKl[n * TSTR + kcol];
                uint32_t bl1 = *(const uint32_t*)&sKl[n * TSTR + kcol + 8];
                MMA_BF16(s[ni], qh[kc][0], qh[kc][1], qh[kc][2], qh[kc][3], bh0, bh1);
                MMA_BF16(s[ni], qh[kc][0], qh[kc][1], qh[kc][2], qh[kc][3], bl0, bl1);
                MMA_BF16(s[ni], ql[kc][0], ql[kc][1], ql[kc][2], ql[kc][3], bh0, bh1);
            }
        }

        // ---- mask ----
        int qi0 = qb * 64 + rowA;
        int qi1 = qi0 + 8;
#pragma unroll
        for (int ni = 0; ni < 8; ni++) {
            int col = kb * 64 + ni * 8 + qc2;
#pragma unroll
            for (int e = 0; e < 4; e++) {
                int kj = col + (e & 1);
                int qi = (e < 2) ? qi0 : qi1;
                bool ok = ba || (kj < WIN) || (kj <= qi && kj + (WIN - 1) >= qi);
                if (!ok) s[ni][e] = -1e30f;
            }
        }

        // ---- online softmax ----
        float mb0 = -1e30f, mb1 = -1e30f;
#pragma unroll
        for (int ni = 0; ni < 8; ni++) {
            mb0 = fmaxf(mb0, fmaxf(s[ni][0], s[ni][1]));
            mb1 = fmaxf(mb1, fmaxf(s[ni][2], s[ni][3]));
        }
        mb0 = fmaxf(mb0, __shfl_xor_sync(0xFFFFFFFF, mb0, 1));
        mb0 = fmaxf(mb0, __shfl_xor_sync(0xFFFFFFFF, mb0, 2));
        mb1 = fmaxf(mb1, __shfl_xor_sync(0xFFFFFFFF, mb1, 1));
        mb1 = fmaxf(mb1, __shfl_xor_sync(0xFFFFFFFF, mb1, 2));

        float mn0 = fmaxf(m0, mb0), mn1 = fmaxf(m1, mb1);
        float sc0 = __expf(m0 - mn0), sc1 = __expf(m1 - mn1);
        m0 = mn0; m1 = mn1;
        l0 *= sc0; l1 *= sc1;
#pragma unroll
        for (int ni = 0; ni < 8; ni++) {
            o[ni][0] *= sc0; o[ni][1] *= sc0;
            o[ni][2] *= sc1; o[ni][3] *= sc1;
        }

#pragma unroll
        for (int ni = 0; ni < 8; ni++) {
            s[ni][0] = __expf(s[ni][0] - m0);
            s[ni][1] = __expf(s[ni][1] - m0);
            s[ni][2] = __expf(s[ni][2] - m1);
            s[ni][3] = __expf(s[ni][3] - m1);
            l0 += s[ni][0] + s[ni][1];
            l1 += s[ni][2] + s[ni][3];
        }

        // ---- O += P V ----
#pragma unroll
        for (int kc = 0; kc < 4; kc++) {
            uint32_t ah[4], al[4];
            cvt2(make_float2(s[2 * kc][0],     s[2 * kc][1]),     ah[0], al[0]);
            cvt2(make_float2(s[2 * kc][2],     s[2 * kc][3]),     ah[1], al[1]);
            cvt2(make_float2(s[2 * kc + 1][0], s[2 * kc + 1][1]), ah[2], al[2]);
            cvt2(make_float2(s[2 * kc + 1][2], s[2 * kc + 1][3]), ah[3], al[3]);
#pragma unroll
            for (int ni = 0; ni < 8; ni++) {
                int n = ni * 8 + qr;
                int kcol = kc * 16 + qc2;
                uint32_t bh0 = *(const uint32_t*)&sVh[n * TSTR + kcol];
                uint32_t bh1 = *(const uint32_t*)&sVh[n * TSTR + kcol + 8];
                uint32_t bl0 = *(const uint32_t*)&sVl[n * TSTR + kcol];
                uint32_t bl1 = *(const uint32_t*)&sVl[n * TSTR + kcol + 8];
                MMA_BF16(o[ni], ah[0], ah[1], ah[2], ah[3], bh0, bh1);
                MMA_BF16(o[ni], ah[0], ah[1], ah[2], ah[3], bl0, bl1);
                MMA_BF16(o[ni], al[0], al[1], al[2], al[3], bh0, bh1);
            }
        }
        __syncthreads();
        cur = nxt;
        stage ^= 1;
    }

    // finalize: reduce l, normalize, write bf16 hi/lo
    l0 += __shfl_xor_sync(0xFFFFFFFF, l0, 1);
    l0 += __shfl_xor_sync(0xFFFFFFFF, l0, 2);
    l1 += __shfl_xor_sync(0xFFFFFFFF, l1, 1);
    l1 += __shfl_xor_sync(0xFFFFFFFF, l1, 2);
    float inv0 = 1.0f / l0, inv1 = 1.0f / l1;

    int qi0 = qb * 64 + rowA;
#pragma unroll
    for (int ni = 0; ni < 8; ni++) {
        int d = ni * 8 + qc2;
        uint32_t hi, lo;
        cvt2(make_float2(o[ni][0] * inv0, o[ni][1] * inv0), hi, lo);
        int idx0 = ((size_t)qi0 * EMB + h * HD + d) >> 1;
        ((uint32_t*)g_oh)[idx0] = hi;
        ((uint32_t*)g_ol)[idx0] = lo;
        cvt2(make_float2(o[ni][2] * inv1, o[ni][3] * inv1), hi, lo);
        int idx1 = ((size_t)(qi0 + 8) * EMB + h * HD + d) >> 1;
        ((uint32_t*)g_oh)[idx1] = hi;
        ((uint32_t*)g_ol)[idx1] = lo;
    }
}

// ---------------------------------------------------------------------------
extern "C" void kernel_launch(void* const* d_in, const int* in_sizes, int n_in,
                              void* d_out, int out_size) {
    const float* hs   = (const float*)d_in[0];
    const float* cosb = (const float*)d_in[1];
    const float* sinb = (const float*)d_in[2];
    const float* Wq   = (const float*)d_in[3];
    const float* Wk   = (const float*)d_in[4];
    const float* Wv   = (const float*)d_in[5];
    const float* Wo   = (const float*)d_in[6];
    const void*  allow = d_in[7];
    float* out = (float*)d_out;

    __nv_bfloat16 *hsh, *hsl, *wqh, *wql, *wkh, *wkl, *wvh, *wvl, *woh, *wol;
    cudaGetSymbolAddress((void**)&hsh, g_hsh);
    cudaGetSymbolAddress((void**)&hsl, g_hsl);
    cudaGetSymbolAddress((void**)&wqh, g_wqh);
    cudaGetSymbolAddress((void**)&wql, g_wql);
    cudaGetSymbolAddress((void**)&wkh, g_wkh);
    cudaGetSymbolAddress((void**)&wkl, g_wkl);
    cudaGetSymbolAddress((void**)&wvh, g_wvh);
    cudaGetSymbolAddress((void**)&wvl, g_wvl);
    cudaGetSymbolAddress((void**)&woh, g_woh);
    cudaGetSymbolAddress((void**)&wol, g_wol);

    cudaFuncSetAttribute(attn_mma_kernel,
                         cudaFuncAttributeMaxDynamicSharedMemorySize, ATT_SMEM);

    decode_mask_kernel<<<1, 256>>>(allow);

    // one-time bf16 hi/lo conversion of GEMM operands
    {
        int n2 = T_SEQ * EMB / 2;
        cvt_hilo<<<(n2 + 255) / 256, 256>>>(hs, hsh, hsl, n2);
        n2 = EMB * EMB / 2;
        cvt_hilo<<<(n2 + 255) / 256, 256>>>(Wq, wqh, wql, n2);
        cvt_hilo<<<(n2 + 255) / 256, 256>>>(Wo, woh, wol, n2);
        n2 = KVD * EMB / 2;
        cvt_hilo<<<(n2 + 255) / 256, 256>>>(Wk, wkh, wkl, n2);
        cvt_hilo<<<(n2 + 255) / 256, 256>>>(Wv, wvh, wvl, n2);
    }

    // Fused QKV projection
    qkv_gemm<<<dim3(24, T_SEQ / 128), 256>>>();

    // RoPE (q, k in place)
    {
        int total = T_SEQ * (NH + NKV) * 32;
        rope_kernel<<<(total + 255) / 256, 256>>>(cosb, sinb);
    }

    // Pre-convert K (post-RoPE) and V for attention
    prep_k_kernel<<<(NKV * T_SEQ * HD + 255) / 256, 256>>>();
    prep_v_kernel<<<(NKV * HD * T_SEQ + 255) / 256, 256>>>();

    // MMA flash attention (double-buffered)
    attn_mma_kernel<<<dim3(NH, NBLK), 128, ATT_SMEM>>>();

    // Output projection
    out_gemm<<<dim3(EMB / 128, T_SEQ / 128), 256>>>(out);
}

// round 9
// speedup vs baseline: 4.0129x; 1.1498x over previous
#include <cuda_runtime.h>
#include <cuda_bf16.h>
#include <math.h>
#include <stdint.h>

// Problem constants (fixed by setup_inputs)
#define T_SEQ 2048
#define EMB   2048
#define NH    32
#define NKV   8
#define HD    64
#define NBLK  32
#define WIN   256
#define KVD   (NKV * HD)   // 512

// fp32 scratch
__device__ float g_q[T_SEQ * NH * HD];     // [t][h][d]
__device__ float g_k[T_SEQ * NKV * HD];    // [t][kv][d]
__device__ float g_v[T_SEQ * NKV * HD];
__device__ int   g_allow[NBLK * NBLK];

// bf16 hi/lo pre-converted operands
__device__ __nv_bfloat16 g_hsh[T_SEQ * EMB], g_hsl[T_SEQ * EMB];
__device__ __nv_bfloat16 g_wqh[EMB * EMB],  g_wql[EMB * EMB];
__device__ __nv_bfloat16 g_wkh[KVD * EMB],  g_wkl[KVD * EMB];
__device__ __nv_bfloat16 g_wvh[KVD * EMB],  g_wvl[KVD * EMB];
__device__ __nv_bfloat16 g_woh[EMB * EMB],  g_wol[EMB * EMB];
__device__ __nv_bfloat16 g_oh[T_SEQ * EMB], g_ol[T_SEQ * EMB];

// attention K/V bf16 hi/lo (K: [kv][t][d], V transposed: [kv][d][t])
__device__ __nv_bfloat16 g_kh[NKV * T_SEQ * HD], g_kl[NKV * T_SEQ * HD];
__device__ __nv_bfloat16 g_vh[NKV * HD * T_SEQ], g_vl[NKV * HD * T_SEQ];

// one extern-shared buffer shared by all dynamic-smem kernels
extern __shared__ char dsm_raw[];

// ---------------------------------------------------------------------------
// Decode rw_allow_blocks robustly (bool/int8 vs int32 vs float32).
// ---------------------------------------------------------------------------
__global__ void decode_mask_kernel(const void* p) {
    __shared__ int cnt0, cnt123;
    int tid = threadIdx.x;
    if (tid == 0) { cnt0 = 0; cnt123 = 0; }
    __syncthreads();
    const unsigned char* b = (const unsigned char*)p;
    int l0 = 0, l123 = 0;
    for (int i = tid; i < 1024; i += 256) {
        if (b[i]) { if ((i & 3) == 0) l0++; else l123++; }
    }
    atomicAdd(&cnt0, l0);
    atomicAdd(&cnt123, l123);
    __syncthreads();
    if (cnt123 == 0) {
        const int* a = (const int*)p;
        for (int i = tid; i < 1024; i += 256) g_allow[i] = (a[i] != 0);
    } else if (cnt0 == 0) {
        const float* a = (const float*)p;
        for (int i = tid; i < 1024; i += 256) g_allow[i] = (a[i] != 0.0f);
    } else {
        for (int i = tid; i < 1024; i += 256) g_allow[i] = (b[i] != 0);
    }
}

// ---------------------------------------------------------------------------
// Shared helpers
// ---------------------------------------------------------------------------
#define MMA_BF16(d, a0, a1, a2, a3, b0, b1)                                   \
    asm volatile(                                                             \
        "mma.sync.aligned.m16n8k16.row.col.f32.bf16.bf16.f32 "                \
        "{%0,%1,%2,%3}, {%4,%5,%6,%7}, {%8,%9}, {%0,%1,%2,%3};"               \
        : "+f"(d[0]), "+f"(d[1]), "+f"(d[2]), "+f"(d[3])                      \
        : "r"(a0), "r"(a1), "r"(a2), "r"(a3), "r"(b0), "r"(b1))

#define LDSM_X4(R0, R1, R2, R3, ADDR)                                         \
    asm volatile("ldmatrix.sync.aligned.m8n8.x4.shared.b16 {%0,%1,%2,%3}, [%4];" \
        : "=r"(R0), "=r"(R1), "=r"(R2), "=r"(R3) : "r"(ADDR))

#define LDSM_X2(R0, R1, ADDR)                                                 \
    asm volatile("ldmatrix.sync.aligned.m8n8.x2.shared.b16 {%0,%1}, [%2];"    \
        : "=r"(R0), "=r"(R1) : "r"(ADDR))

__device__ __forceinline__ void cp16(uint32_t saddr, const void* g) {
    asm volatile("cp.async.cg.shared.global [%0], [%1], 16;" :: "r"(saddr), "l"(g));
}
__device__ __forceinline__ void cp_commit() {
    asm volatile("cp.async.commit_group;" ::: "memory");
}

__device__ __forceinline__ void cvt2(float2 f, uint32_t& hi, uint32_t& lo) {
    __nv_bfloat162 h = __floats2bfloat162_rn(f.x, f.y);
    hi = *reinterpret_cast<uint32_t*>(&h);
    __nv_bfloat162 l = __floats2bfloat162_rn(f.x - __bfloat162float(h.x),
                                             f.y - __bfloat162float(h.y));
    lo = *reinterpret_cast<uint32_t*>(&l);
}

__device__ __forceinline__ uint32_t smem_u32(const void* p) {
    return (uint32_t)__cvta_generic_to_shared(p);
}

// fp32 -> bf16 hi/lo, 2 elements per thread
__global__ void cvt_hilo(const float* __restrict__ src,
                         __nv_bfloat16* __restrict__ h,
                         __nv_bfloat16* __restrict__ l, int n2) {
    int i = blockIdx.x * blockDim.x + threadIdx.x;
    if (i >= n2) return;
    float2 v = ((const float2*)src)[i];
    uint32_t hi, lo;
    cvt2(v, hi, lo);
    ((uint32_t*)h)[i] = hi;
    ((uint32_t*)l)[i] = lo;
}

// ---------------------------------------------------------------------------
// GEMM v4: C[M,N] = A[M,K] * B[N,K]^T, pre-split bf16 hi/lo, ldmatrix frags.
// Block 128x128, BK=32, dynamic smem (2 stages x 40KB), cp.async pipeline.
// Row stride 80B: LDSM 16B-phase banks 5*row mod 8 -> conflict-free.
// ---------------------------------------------------------------------------
#define TPADH      40                       // halves per row (32 data + 8 pad)
#define G3_ROW_B   (TPADH * 2)              // 80 bytes
#define G3_TILE_B  (128 * G3_ROW_B)         // 10240
#define G3_STAGE_B (4 * G3_TILE_B)          // 40960
#define G3_SMEM    (2 * G3_STAGE_B)         // 81920

__device__ __forceinline__ void gemm3_core(
    const __nv_bfloat16* __restrict__ Ah, const __nv_bfloat16* __restrict__ Al,
    const __nv_bfloat16* __restrict__ Bh, const __nv_bfloat16* __restrict__ Bl,
    float* __restrict__ C, int K, int ldc, int m0, int n0)
{
    uint32_t sbase = smem_u32(dsm_raw);

    int tid  = threadIdx.x;
    int warp = tid >> 5;
    int lane = tid & 31;
    int wm = warp & 1;
    int wn = warp >> 1;
    int qr = lane >> 2;
    int qc2 = (lane & 3) * 2;

    float acc[4][4][4];
#pragma unroll
    for (int i = 0; i < 4; i++)
#pragma unroll
        for (int j = 0; j < 4; j++)
#pragma unroll
            for (int e = 0; e < 4; e++) acc[i][j][e] = 0.0f;

    // fill: 2048 16B-chunks per stage, 8 per thread
    const __nv_bfloat16* srcs[4];
    srcs[0] = Ah + (size_t)m0 * K;
    srcs[1] = Al + (size_t)m0 * K;
    srcs[2] = Bh + (size_t)n0 * K;
    srcs[3] = Bl + (size_t)n0 * K;

    // ldmatrix per-thread base offsets (byte offsets inside a tile)
    int arow = wm * 64 + (lane & 7) + ((lane >> 3) & 1) * 8;
    uint32_t aOff = arow * G3_ROW_B + ((lane >> 4) & 1) * 16;
    int brow = wn * 32 + (lane & 7);
    uint32_t bOff = brow * G3_ROW_B + ((lane >> 3) & 1) * 16;

    const int NITER = K / 32;

    // prologue: fill stage 0
    {
        uint32_t sb = sbase;
#pragma unroll
        for (int t = 0; t < 8; t++) {
            int id = t * 256 + tid;
            int tile = id >> 9;
            int row  = (id >> 2) & 127;
            int c    = id & 3;
            cp16(sb + tile * G3_TILE_B + row * G3_ROW_B + c * 16,
                 srcs[tile] + (size_t)row * K + c * 8);
        }
        cp_commit();
    }

    for (int it = 0; it < NITER; it++) {
        if (it + 1 < NITER) {
            int k0 = (it + 1) * 32;
            uint32_t sb = sbase + ((it + 1) & 1) * G3_STAGE_B;
#pragma unroll
            for (int t = 0; t < 8; t++) {
                int id = t * 256 + tid;
                int tile = id >> 9;
                int row  = (id >> 2) & 127;
                int c    = id & 3;
                cp16(sb + tile * G3_TILE_B + row * G3_ROW_B + c * 16,
                     srcs[tile] + (size_t)row * K + k0 + c * 8);
            }
            cp_commit();
            asm volatile("cp.async.wait_group 1;" ::: "memory");
        } else {
            asm volatile("cp.async.wait_group 0;" ::: "memory");
        }
        __syncthreads();

        uint32_t sb = sbase + (it & 1) * G3_STAGE_B;
        uint32_t tAh = sb, tAl = sb + G3_TILE_B;
        uint32_t tBh = sb + 2 * G3_TILE_B, tBl = sb + 3 * G3_TILE_B;

#pragma unroll
        for (int k1 = 0; k1 < 2; k1++) {
            uint32_t ko = k1 * 32;   // 16 halves = 32 bytes
            uint32_t ah[4][4], al[4][4];
#pragma unroll
            for (int mi = 0; mi < 4; mi++) {
                uint32_t off = aOff + mi * (16 * G3_ROW_B) + ko;
                LDSM_X4(ah[mi][0], ah[mi][1], ah[mi][2], ah[mi][3], tAh + off);
                LDSM_X4(al[mi][0], al[mi][1], al[mi][2], al[mi][3], tAl + off);
            }
#pragma unroll
            for (int ni = 0; ni < 4; ni++) {
                uint32_t off = bOff + ni * (8 * G3_ROW_B) + ko;
                uint32_t bh0, bh1, bl0, bl1;
                LDSM_X2(bh0, bh1, tBh + off);
                LDSM_X2(bl0, bl1, tBl + off);
#pragma unroll
                for (int mi = 0; mi < 4; mi++) {
                    MMA_BF16(acc[mi][ni], ah[mi][0], ah[mi][1], ah[mi][2], ah[mi][3], bh0, bh1);
                    MMA_BF16(acc[mi][ni], ah[mi][0], ah[mi][1], ah[mi][2], ah[mi][3], bl0, bl1);
                    MMA_BF16(acc[mi][ni], al[mi][0], al[mi][1], al[mi][2], al[mi][3], bh0, bh1);
                }
            }
        }
        __syncthreads();
    }

    // epilogue
#pragma unroll
    for (int mi = 0; mi < 4; mi++) {
#pragma unroll
        for (int ni = 0; ni < 4; ni++) {
            int r = m0 + wm * 64 + mi * 16 + qr;
            int cidx = n0 + wn * 32 + ni * 8 + qc2;
            *(float2*)&C[(size_t)r * ldc + cidx] =
                make_float2(acc[mi][ni][0], acc[mi][ni][1]);
            *(float2*)&C[(size_t)(r + 8) * ldc + cidx] =
                make_float2(acc[mi][ni][2], acc[mi][ni][3]);
        }
    }
}

__global__ __launch_bounds__(256, 2)
void qkv_gemm() {
    int bx = blockIdx.x;
    int m0 = blockIdx.y * 128;
    if (bx < 16)
        gemm3_core(g_hsh, g_hsl, g_wqh, g_wql, g_q, EMB, EMB, m0, bx * 128);
    else if (bx < 20)
        gemm3_core(g_hsh, g_hsl, g_wkh, g_wkl, g_k, EMB, KVD, m0, (bx - 16) * 128);
    else
        gemm3_core(g_hsh, g_hsl, g_wvh, g_wvl, g_v, EMB, KVD, m0, (bx - 20) * 128);
}

__global__ __launch_bounds__(256, 2)
void out_gemm(float* __restrict__ out) {
    gemm3_core(g_oh, g_ol, g_woh, g_wol, out, EMB, EMB,
               blockIdx.y * 128, blockIdx.x * 128);
}

// ---------------------------------------------------------------------------
// RoPE applied in-place to q and k.
// ---------------------------------------------------------------------------
__global__ void rope_kernel(const float* __restrict__ cosb, const float* __restrict__ sinb) {
    int idx = blockIdx.x * blockDim.x + threadIdx.x;
    const int total = T_SEQ * (NH + NKV) * 32;
    if (idx >= total) return;
    int d = idx & 31;
    int rest = idx >> 5;
    int head = rest % (NH + NKV);
    int t = rest / (NH + NKV);
    float c0 = cosb[t * HD + d];
    float s0 = sinb[t * HD + d];
    float c1 = cosb[t * HD + d + 32];
    float s1 = sinb[t * HD + d + 32];
    float* base = (head < NH) ? (g_q + ((size_t)t * NH + head) * HD)
                              : (g_k + ((size_t)t * NKV + (head - NH)) * HD);
    float x0 = base[d];
    float x1 = base[d + 32];
    base[d]      = x0 * c0 - x1 * s0;
    base[d + 32] = x1 * c1 + x0 * s1;
}

// ---------------------------------------------------------------------------
// Prep: K (post-RoPE) -> bf16 hi/lo [kv][t][d]; V -> transposed [kv][d][t].
// ---------------------------------------------------------------------------
__global__ void prep_k_kernel() {
    int o = blockIdx.x * blockDim.x + threadIdx.x;
    if (o >= NKV * T_SEQ * HD) return;
    int d  = o & 63;
    int t  = (o >> 6) & (T_SEQ - 1);
    int kv = o >> 17;
    float v = g_k[((size_t)t * NKV + kv) * HD + d];
    __nv_bfloat16 h = __float2bfloat16(v);
    g_kh[o] = h;
    g_kl[o] = __float2bfloat16(v - __bfloat162float(h));
}

__global__ void prep_v_kernel() {
    int o = blockIdx.x * blockDim.x + threadIdx.x;
    if (o >= NKV * HD * T_SEQ) return;
    int t  = o & (T_SEQ - 1);
    int d  = (o >> 11) & 63;
    int kv = o >> 17;
    float v = g_v[((size_t)t * NKV + kv) * HD + d];
    __nv_bfloat16 h = __float2bfloat16(v);
    g_vh[o] = h;
    g_vl[o] = __float2bfloat16(v - __bfloat162float(h));
}

// ---------------------------------------------------------------------------
// MMA flash attention with double-buffered kb tiles (dynamic smem, 2 stages).
// ---------------------------------------------------------------------------
#define TSTR 72
#define ATT_TILE   (64 * TSTR)
#define ATT_STAGE  (4 * ATT_TILE)
#define ATT_SMEM   (2 * ATT_STAGE * 2)

__device__ __forceinline__ void att_issue_loads(__nv_bfloat16* att_dsm,
                                                int stage, int kb, int kv, int tid) {
    uint32_t base = smem_u32(att_dsm + stage * ATT_STAGE);
#pragma unroll
    for (int t = 0; t < 16; t++) {
        int id   = t * 128 + tid;
        int tile = id >> 9;
        int row  = (id >> 3) & 63;
        int ch   = id & 7;
        const __nv_bfloat16* src;
        if (tile == 0)
            src = g_kh + (((size_t)kv * T_SEQ + kb * 64 + row) * HD + ch * 8);
        else if (tile == 1)
            src = g_kl + (((size_t)kv * T_SEQ + kb * 64 + row) * HD + ch * 8);
        else if (tile == 2)
            src = g_vh + (((size_t)kv * HD + row) * T_SEQ + kb * 64 + ch * 8);
        else
            src = g_vl + (((size_t)kv * HD + row) * T_SEQ + kb * 64 + ch * 8);
        cp16(base + (tile * ATT_TILE + row * TSTR + ch * 8) * 2, src);
    }
    cp_commit();
}

__global__ __launch_bounds__(128)
void attn_mma_kernel() {
    __nv_bfloat16* att_dsm = (__nv_bfloat16*)dsm_raw;
    int h  = blockIdx.x;
    int qb = blockIdx.y;
    int kv = h >> 2;
    int tid  = threadIdx.x;
    int w    = tid >> 5;
    int lane = tid & 31;
    int qr   = lane >> 2;
    int qc2  = (lane & 3) * 2;
    int rowA = w * 16 + qr;

    // stage Q (fp32, pre-scaled) in stage-0 region, build A-frags, release
    float* sQ = (float*)att_dsm;
    for (int i = tid; i < 64 * 16; i += 128) {
        int row = i >> 4;
        int c4  = (i & 15) * 4;
        float4 v = *(const float4*)&g_q[(((size_t)qb * 64 + row) * NH + h) * HD + c4];
        v.x *= 0.125f; v.y *= 0.125f; v.z *= 0.125f; v.w *= 0.125f;
        *(float4*)&sQ[row * 68 + c4] = v;
    }
    __syncthreads();

    uint32_t qh[4][4], ql[4][4];
#pragma unroll
    for (int kc = 0; kc < 4; kc++) {
        int k = kc * 16 + qc2;
        cvt2(*(const float2*)&sQ[rowA * 68 + k],           qh[kc][0], ql[kc][0]);
        cvt2(*(const float2*)&sQ[(rowA + 8) * 68 + k],     qh[kc][1], ql[kc][1]);
        cvt2(*(const float2*)&sQ[rowA * 68 + k + 8],       qh[kc][2], ql[kc][2]);
        cvt2(*(const float2*)&sQ[(rowA + 8) * 68 + k + 8], qh[kc][3], ql[kc][3]);
    }
    __syncthreads();

    float m0 = -1e30f, m1 = -1e30f, l0 = 0.0f, l1 = 0.0f;
    float o[8][4];
#pragma unroll
    for (int ni = 0; ni < 8; ni++)
#pragma unroll
        for (int e = 0; e < 4; e++) o[ni][e] = 0.0f;

    int cur = 0, stage = 0;
    att_issue_loads(att_dsm, 0, 0, kv, tid);

    while (cur < NBLK) {
        int nxt = cur + 1;
        while (nxt < NBLK) {
            if (g_allow[qb * NBLK + nxt] || (nxt < 4) ||
                (nxt <= qb && nxt + 4 >= qb)) break;
            nxt++;
        }
        if (nxt < NBLK) {
            att_issue_loads(att_dsm, stage ^ 1, nxt, kv, tid);
            asm volatile("cp.async.wait_group 1;" ::: "memory");
        } else {
            asm volatile("cp.async.wait_group 0;" ::: "memory");
        }
        __syncthreads();

        int kb = cur;
        int ba = g_allow[qb * NBLK + kb];
        const __nv_bfloat16* sKh = att_dsm + stage * ATT_STAGE;
        const __nv_bfloat16* sKl = sKh + ATT_TILE;
        const __nv_bfloat16* sVh = sKl + ATT_TILE;
        const __nv_bfloat16* sVl = sVh + ATT_TILE;

        float s[8][4];
#pragma unroll
        for (int ni = 0; ni < 8; ni++) {
#pragma unroll
            for (int e = 0; e < 4; e++) s[ni][e] = 0.0f;
            int n = ni * 8 + qr;
#pragma unroll
            for (int kc = 0; kc < 4; kc++) {
                int kcol = kc * 16 + qc2;
                uint32_t bh0 = *(const uint32_t*)&sKh[n * TSTR + kcol];
                uint32_t bh1 = *(const uint32_t*)&sKh[n * TSTR + kcol + 8];
                uint32_t bl0 = *(const uint32_t*)&sKl[n * TSTR + kcol];
                uint32_t bl1 = *(const uint32_t*)&sKl[n * TSTR + kcol + 8];
                MMA_BF16(s[ni], qh[kc][0], qh[kc][1], qh[kc][2], qh[kc][3], bh0, bh1);
                MMA_BF16(s[ni], qh[kc][0], qh[kc][1], qh[kc][2], qh[kc][3], bl0, bl1);
                MMA_BF16(s[ni], ql[kc][0], ql[kc][1], ql[kc][2], ql[kc][3], bh0, bh1);
            }
        }

        int qi0 = qb * 64 + rowA;
        int qi1 = qi0 + 8;
#pragma unroll
        for (int ni = 0; ni < 8; ni++) {
            int col = kb * 64 + ni * 8 + qc2;
#pragma unroll
            for (int e = 0; e < 4; e++) {
                int kj = col + (e & 1);
                int qi = (e < 2) ? qi0 : qi1;
                bool ok = ba || (kj < WIN) || (kj <= qi && kj + (WIN - 1) >= qi);
                if (!ok) s[ni][e] = -1e30f;
            }
        }

        float mb0 = -1e30f, mb1 = -1e30f;
#pragma unroll
        for (int ni = 0; ni < 8; ni++) {
            mb0 = fmaxf(mb0, fmaxf(s[ni][0], s[ni][1]));
            mb1 = fmaxf(mb1, fmaxf(s[ni][2], s[ni][3]));
        }
        mb0 = fmaxf(mb0, __shfl_xor_sync(0xFFFFFFFF, mb0, 1));
        mb0 = fmaxf(mb0, __shfl_xor_sync(0xFFFFFFFF, mb0, 2));
        mb1 = fmaxf(mb1, __shfl_xor_sync(0xFFFFFFFF, mb1, 1));
        mb1 = fmaxf(mb1, __shfl_xor_sync(0xFFFFFFFF, mb1, 2));

        float mn0 = fmaxf(m0, mb0), mn1 = fmaxf(m1, mb1);
        float sc0 = __expf(m0 - mn0), sc1 = __expf(m1 - mn1);
        m0 = mn0; m1 = mn1;
        l0 *= sc0; l1 *= sc1;
#pragma unroll
        for (int ni = 0; ni < 8; ni++) {
            o[ni][0] *= sc0; o[ni][1] *= sc0;
            o[ni][2] *= sc1; o[ni][3] *= sc1;
        }

#pragma unroll
        for (int ni = 0; ni < 8; ni++) {
            s[ni][0] = __expf(s[ni][0] - m0);
            s[ni][1] = __expf(s[ni][1] - m0);
            s[ni][2] = __expf(s[ni][2] - m1);
            s[ni][3] = __expf(s[ni][3] - m1);
            l0 += s[ni][0] + s[ni][1];
            l1 += s[ni][2] + s[ni][3];
        }

#pragma unroll
        for (int kc = 0; kc < 4; kc++) {
            uint32_t ah[4], al[4];
            cvt2(make_float2(s[2 * kc][0],     s[2 * kc][1]),     ah[0], al[0]);
            cvt2(make_float2(s[2 * kc][2],     s[2 * kc][3]),     ah[1], al[1]);
            cvt2(make_float2(s[2 * kc + 1][0], s[2 * kc + 1][1]), ah[2], al[2]);
            cvt2(make_float2(s[2 * kc + 1][2], s[2 * kc + 1][3]), ah[3], al[3]);
#pragma unroll
            for (int ni = 0; ni < 8; ni++) {
                int n = ni * 8 + qr;
                int kcol = kc * 16 + qc2;
                uint32_t bh0 = *(const uint32_t*)&sVh[n * TSTR + kcol];
                uint32_t bh1 = *(const uint32_t*)&sVh[n * TSTR + kcol + 8];
                uint32_t bl0 = *(const uint32_t*)&sVl[n * TSTR + kcol];
                uint32_t bl1 = *(const uint32_t*)&sVl[n * TSTR + kcol + 8];
                MMA_BF16(o[ni], ah[0], ah[1], ah[2], ah[3], bh0, bh1);
                MMA_BF16(o[ni], ah[0], ah[1], ah[2], ah[3], bl0, bl1);
                MMA_BF16(o[ni], al[0], al[1], al[2], al[3], bh0, bh1);
            }
        }
        __syncthreads();
        cur = nxt;
        stage ^= 1;
    }

    l0 += __shfl_xor_sync(0xFFFFFFFF, l0, 1);
    l0 += __shfl_xor_sync(0xFFFFFFFF, l0, 2);
    l1 += __shfl_xor_sync(0xFFFFFFFF, l1, 1);
    l1 += __shfl_xor_sync(0xFFFFFFFF, l1, 2);
    float inv0 = 1.0f / l0, inv1 = 1.0f / l1;

    int qi0 = qb * 64 + rowA;
#pragma unroll
    for (int ni = 0; ni < 8; ni++) {
        int d = ni * 8 + qc2;
        uint32_t hi, lo;
        cvt2(make_float2(o[ni][0] * inv0, o[ni][1] * inv0), hi, lo);
        int idx0 = ((size_t)qi0 * EMB + h * HD + d) >> 1;
        ((uint32_t*)g_oh)[idx0] = hi;
        ((uint32_t*)g_ol)[idx0] = lo;
        cvt2(make_float2(o[ni][2] * inv1, o[ni][3] * inv1), hi, lo);
        int idx1 = ((size_t)(qi0 + 8) * EMB + h * HD + d) >> 1;
        ((uint32_t*)g_oh)[idx1] = hi;
        ((uint32_t*)g_ol)[idx1] = lo;
    }
}

// ---------------------------------------------------------------------------
extern "C" void kernel_launch(void* const* d_in, const int* in_sizes, int n_in,
                              void* d_out, int out_size) {
    const float* hs   = (const float*)d_in[0];
    const float* cosb = (const float*)d_in[1];
    const float* sinb = (const float*)d_in[2];
    const float* Wq   = (const float*)d_in[3];
    const float* Wk   = (const float*)d_in[4];
    const float* Wv   = (const float*)d_in[5];
    const float* Wo   = (const float*)d_in[6];
    const void*  allow = d_in[7];
    float* out = (float*)d_out;

    __nv_bfloat16 *hsh, *hsl, *wqh, *wql, *wkh, *wkl, *wvh, *wvl, *woh, *wol;
    cudaGetSymbolAddress((void**)&hsh, g_hsh);
    cudaGetSymbolAddress((void**)&hsl, g_hsl);
    cudaGetSymbolAddress((void**)&wqh, g_wqh);
    cudaGetSymbolAddress((void**)&wql, g_wql);
    cudaGetSymbolAddress((void**)&wkh, g_wkh);
    cudaGetSymbolAddress((void**)&wkl, g_wkl);
    cudaGetSymbolAddress((void**)&wvh, g_wvh);
    cudaGetSymbolAddress((void**)&wvl, g_wvl);
    cudaGetSymbolAddress((void**)&woh, g_woh);
    cudaGetSymbolAddress((void**)&wol, g_wol);

    cudaFuncSetAttribute(attn_mma_kernel,
                         cudaFuncAttributeMaxDynamicSharedMemorySize, ATT_SMEM);
    cudaFuncSetAttribute(qkv_gemm,
                         cudaFuncAttributeMaxDynamicSharedMemorySize, G3_SMEM);
    cudaFuncSetAttribute(out_gemm,
                         cudaFuncAttributeMaxDynamicSharedMemorySize, G3_SMEM);

    // one-time bf16 hi/lo conversion of GEMM operands (launches 0-4, so the
    // ncu capture window -s 5 -c 1 lands on qkv_gemm)
    {
        int n2 = T_SEQ * EMB / 2;
        cvt_hilo<<<(n2 + 255) / 256, 256>>>(hs, hsh, hsl, n2);
        n2 = EMB * EMB / 2;
        cvt_hilo<<<(n2 + 255) / 256, 256>>>(Wq, wqh, wql, n2);
        cvt_hilo<<<(n2 + 255) / 256, 256>>>(Wo, woh, wol, n2);
        n2 = KVD * EMB / 2;
        cvt_hilo<<<(n2 + 255) / 256, 256>>>(Wk, wkh, wkl, n2);
        cvt_hilo<<<(n2 + 255) / 256, 256>>>(Wv, wvh, wvl, n2);
    }

    // Fused QKV projection (launch index 5)
    qkv_gemm<<<dim3(24, T_SEQ / 128), 256, G3_SMEM>>>();

    // RoPE (q, k in place)
    {
        int total = T_SEQ * (NH + NKV) * 32;
        rope_kernel<<<(total + 255) / 256, 256>>>(cosb, sinb);
    }

    // Pre-convert K (post-RoPE) and V for attention
    prep_k_kernel<<<(NKV * T_SEQ * HD + 255) / 256, 256>>>();
    prep_v_kernel<<<(NKV * HD * T_SEQ + 255) / 256, 256>>>();

    // Mask decode (only needed before attention)
    decode_mask_kernel<<<1, 256>>>(allow);

    // MMA flash attention (double-buffered)
    attn_mma_kernel<<<dim3(NH, NBLK), 128, ATT_SMEM>>>();

    // Output projection
    out_gemm<<<dim3(EMB / 128, T_SEQ / 128), 256, G3_SMEM>>>(out);
}